// round 8
// baseline (speedup 1.0000x reference)
#include <cuda_runtime.h>
#include <math.h>
#include <math_constants.h>

// Problem constants
#define Bq  2
#define Tq  1024
#define Dq  1024
#define Hq  16
#define FFq 4096
#define Lq  8
#define Vq  32000
#define HDq 64
#define Rq  (Bq * Tq)   // 2048 rows

// ---------------------------------------------------------------------------
// Scratch (device globals; no runtime allocation allowed)
// ---------------------------------------------------------------------------
__device__ float g_x  [Rq * Dq];
__device__ float g_ln [Rq * Dq];
__device__ float g_qkv[Rq * 3 * Dq];
__device__ float g_y  [Rq * Dq];
__device__ float g_ff [Rq * FFq];

// tf32-rounded weight copies
__device__ float g_wqkv[Lq * Dq * 3 * Dq];
__device__ float g_wout[Lq * Dq * Dq];
__device__ float g_wm1 [Lq * Dq * FFq];
__device__ float g_wm2 [Lq * FFq * Dq];
__device__ float g_whd [Dq * Vq];

// ---------------------------------------------------------------------------
__device__ __forceinline__ unsigned f2tf(float x) {
    unsigned r;
    asm("cvt.rna.tf32.f32 %0, %1;" : "=r"(r) : "f"(x));
    return r;
}
__device__ __forceinline__ float round_tf(float x) {
    return __uint_as_float(f2tf(x));
}

__global__ void round4_kernel(const float4* __restrict__ in,
                              float4* __restrict__ out, int n4) {
    int i = blockIdx.x * blockDim.x + threadIdx.x;
    if (i < n4) {
        float4 v = in[i];
        out[i] = make_float4(round_tf(v.x), round_tf(v.y),
                             round_tf(v.z), round_tf(v.w));
    }
}

// ---------------------------------------------------------------------------
__device__ __forceinline__ float block_sum(float v, float* sh) {
    int lane = threadIdx.x & 31, w = threadIdx.x >> 5, nw = blockDim.x >> 5;
    #pragma unroll
    for (int o = 16; o; o >>= 1) v += __shfl_xor_sync(0xffffffffu, v, o);
    if (lane == 0) sh[w] = v;
    __syncthreads();
    if (w == 0) {
        v = (lane < nw) ? sh[lane] : 0.0f;
        #pragma unroll
        for (int o = 16; o; o >>= 1) v += __shfl_xor_sync(0xffffffffu, v, o);
        if (lane == 0) sh[0] = v;
    }
    __syncthreads();
    float r = sh[0];
    __syncthreads();
    return r;
}

// ---------------------------------------------------------------------------
__global__ void embed_kernel(const int* __restrict__ idx,
                             const float* __restrict__ emb,
                             float* __restrict__ x) {
    int row = blockIdx.x;
    int t   = row % Tq;
    int tok = idx[row];
    const float* er = emb + (size_t)tok * Dq;
    const float neg_log = -logf(10000.0f) / (float)Dq;
    for (int d = threadIdx.x; d < Dq; d += blockDim.x) {
        int i2 = d & ~1;
        float freq = expf(neg_log * (float)i2);
        float ang  = (float)t * freq;
        float pe   = (d & 1) ? cosf(ang) : sinf(ang);
        x[(size_t)row * Dq + d] = er[d] + pe;
    }
}

// ---------------------------------------------------------------------------
__global__ void ln_kernel(const float* __restrict__ x,
                          const float* __restrict__ sc,
                          const float* __restrict__ bi,
                          float* __restrict__ out) {
    __shared__ float sh[32];
    int row = blockIdx.x;
    const float* xr = x + (size_t)row * Dq;
    float v[4];
    float lsum = 0.0f;
    #pragma unroll
    for (int i = 0; i < 4; i++) {
        v[i] = xr[threadIdx.x + i * 256];
        lsum += v[i];
    }
    float mean = block_sum(lsum, sh) * (1.0f / (float)Dq);
    float lsq = 0.0f;
    #pragma unroll
    for (int i = 0; i < 4; i++) {
        float d = v[i] - mean;
        lsq += d * d;
    }
    float var = block_sum(lsq, sh) * (1.0f / (float)Dq);
    float inv = rsqrtf(var + 1e-5f);
    #pragma unroll
    for (int i = 0; i < 4; i++) {
        int d = threadIdx.x + i * 256;
        out[(size_t)row * Dq + d] = round_tf((v[i] - mean) * inv * sc[d] + bi[d]);
    }
}

// ---------------------------------------------------------------------------
// TF32 tensor-core GEMM, cp.async double-buffer.
// Template over BN (128 or 256) and NT (threads). Warp tile 64x64 always.
//   BN=128, NT=128: 4 warps (2x2)  — proven R5/R6 config.
//   BN=256, NT=256: 8 warps (2x4)  — halves A-panel L2 traffic for large N.
// ---------------------------------------------------------------------------
__device__ __forceinline__ void mma_tf32(float c[4],
                                         unsigned a0, unsigned a1, unsigned a2, unsigned a3,
                                         unsigned b0, unsigned b1) {
    asm volatile(
        "mma.sync.aligned.m16n8k8.row.col.f32.tf32.tf32.f32 "
        "{%0,%1,%2,%3}, {%4,%5,%6,%7}, {%8,%9}, {%0,%1,%2,%3};"
        : "+f"(c[0]), "+f"(c[1]), "+f"(c[2]), "+f"(c[3])
        : "r"(a0), "r"(a1), "r"(a2), "r"(a3), "r"(b0), "r"(b1));
}

#define CP16(dst, src) \
    asm volatile("cp.async.cg.shared.global [%0], [%1], 16;\n" :: "r"(dst), "l"(src))

template <int EPI, int BN, int NT>
__global__ __launch_bounds__(NT)
void tgemm_kernel(const float* __restrict__ A, const float* __restrict__ B,
                  const float* __restrict__ bias, float* __restrict__ C,
                  int M, int N, int K) {
    constexpr int BM = 128, BK = 32;
    constexpr int ASZ = BM * BK;
    constexpr int BSZ = BK * BN;
    // copy mapping
    constexpr int TPR_B = BN / 4;       // threads per B row (float4)
    constexpr int RPP_B = NT / TPR_B;   // B rows per pass (=4)
    constexpr int IT_B  = 32 / RPP_B;   // 8
    constexpr int RPP_A = NT / 8;       // A rows per pass
    constexpr int IT_A  = 128 / RPP_A;

    extern __shared__ float smf[];
    float* Abuf = smf;
    float* Bbuf = smf + 2 * ASZ;

    int tid  = threadIdx.x;
    int lane = tid & 31;
    int warp = tid >> 5;
    int g    = lane >> 2;
    int tig  = lane & 3;
    int wm   = warp & 1;
    int wn   = warp >> 1;
    int rm   = wm * 64;
    int cn   = wn * 64;
    unsigned xora = (unsigned)(g << 2);
    unsigned xorb = (unsigned)(tig << 3);

    const float* Ab = A + (size_t)(blockIdx.y * BM) * K;
    const float* Bb = B + (size_t)(blockIdx.x) * BN;

    float acc[4][8][4];
    #pragma unroll
    for (int mi = 0; mi < 4; mi++)
        #pragma unroll
        for (int ni = 0; ni < 8; ni++)
            #pragma unroll
            for (int c = 0; c < 4; c++) acc[mi][ni][c] = 0.0f;

    int a_m  = tid >> 3;
    int a_k4 = (tid & 7) << 2;
    int b_k  = tid / TPR_B;
    int b_n4 = (tid % TPR_B) << 2;
    unsigned xsta = (unsigned)((a_m & 7) << 2);
    unsigned xstb = (unsigned)((b_k & 3) << 3);

    unsigned sA0 = (unsigned)__cvta_generic_to_shared(Abuf);
    unsigned sB0 = (unsigned)__cvta_generic_to_shared(Bbuf);

    auto issue = [&](int kt, int p) {
        unsigned sa = sA0 + (unsigned)(p * ASZ) * 4u;
        unsigned sb = sB0 + (unsigned)(p * BSZ) * 4u;
        #pragma unroll
        for (int i = 0; i < IT_A; i++) {
            int m = i * RPP_A + a_m;
            const float* src = Ab + (size_t)m * K + kt + a_k4;
            unsigned dst = sa + (unsigned)(m * 32 + ((unsigned)a_k4 ^ xsta)) * 4u;
            CP16(dst, src);
        }
        #pragma unroll
        for (int i = 0; i < IT_B; i++) {
            int k = i * RPP_B + b_k;
            const float* src = Bb + (size_t)(kt + k) * N + b_n4;
            unsigned dst = sb + (unsigned)(k * BN + ((unsigned)b_n4 ^ xstb)) * 4u;
            CP16(dst, src);
        }
        asm volatile("cp.async.commit_group;\n");
    };

    issue(0, 0);

    int ntiles = K / BK;
    for (int t = 0; t < ntiles; t++) {
        int p = t & 1;
        asm volatile("cp.async.wait_group 0;\n");
        __syncthreads();
        if (t + 1 < ntiles) issue((t + 1) * BK, p ^ 1);

        const float* Ap = Abuf + p * ASZ;
        const float* Bp = Bbuf + p * BSZ;
        #pragma unroll
        for (int ks = 0; ks < 4; ks++) {
            int k0 = ks * 8;
            unsigned af[4][4], bf[8][2];
            unsigned ka0 = (unsigned)(k0 + tig)     ^ xora;
            unsigned ka1 = (unsigned)(k0 + tig + 4) ^ xora;
            #pragma unroll
            for (int mi = 0; mi < 4; mi++) {
                int m1 = rm + mi * 16 + g;
                int m2 = m1 + 8;
                af[mi][0] = __float_as_uint(Ap[m1 * 32 + ka0]);
                af[mi][1] = __float_as_uint(Ap[m2 * 32 + ka0]);
                af[mi][2] = __float_as_uint(Ap[m1 * 32 + ka1]);
                af[mi][3] = __float_as_uint(Ap[m2 * 32 + ka1]);
            }
            #pragma unroll
            for (int ni = 0; ni < 8; ni++) {
                unsigned nb = (unsigned)(cn + ni * 8 + g) ^ xorb;
                bf[ni][0] = __float_as_uint(Bp[(k0 + tig)     * BN + nb]);
                bf[ni][1] = __float_as_uint(Bp[(k0 + tig + 4) * BN + nb]);
            }
            #pragma unroll
            for (int mi = 0; mi < 4; mi++)
                #pragma unroll
                for (int ni = 0; ni < 8; ni++)
                    mma_tf32(acc[mi][ni],
                             af[mi][0], af[mi][1], af[mi][2], af[mi][3],
                             bf[ni][0], bf[ni][1]);
        }
        __syncthreads();
    }

    #pragma unroll
    for (int ni = 0; ni < 8; ni++) {
        int gc = blockIdx.x * BN + cn + ni * 8 + 2 * tig;
        float bv0 = bias ? bias[gc]     : 0.0f;
        float bv1 = bias ? bias[gc + 1] : 0.0f;
        #pragma unroll
        for (int mi = 0; mi < 4; mi++) {
            int gr1 = blockIdx.y * BM + rm + mi * 16 + g;
            int gr2 = gr1 + 8;
            float v00 = acc[mi][ni][0] + bv0;
            float v01 = acc[mi][ni][1] + bv1;
            float v10 = acc[mi][ni][2] + bv0;
            float v11 = acc[mi][ni][3] + bv1;
            float* p1 = C + (size_t)gr1 * N + gc;
            float* p2 = C + (size_t)gr2 * N + gc;
            if (EPI == 0) {
                *(float2*)p1 = make_float2(v00, v01);
                *(float2*)p2 = make_float2(v10, v11);
            } else if (EPI == 1) {
                float2 o1 = *(const float2*)p1;
                float2 o2 = *(const float2*)p2;
                *(float2*)p1 = make_float2(o1.x + v00, o1.y + v01);
                *(float2*)p2 = make_float2(o2.x + v10, o2.y + v11);
            } else {
                const float is2 = 0.70710678118654752f;
                *(float2*)p1 = make_float2(
                    round_tf(0.5f * v00 * (1.0f + erff(v00 * is2))),
                    round_tf(0.5f * v01 * (1.0f + erff(v01 * is2))));
                *(float2*)p2 = make_float2(
                    round_tf(0.5f * v10 * (1.0f + erff(v10 * is2))),
                    round_tf(0.5f * v11 * (1.0f + erff(v11 * is2))));
            }
        }
    }
}

// ---------------------------------------------------------------------------
// Tensor-core flash attention (unchanged from R6 — proven).
// ---------------------------------------------------------------------------
#define QPAD 68
#define VPAD 72

__global__ __launch_bounds__(128)
void attn3_kernel(const float* __restrict__ qkv, float* __restrict__ y) {
    extern __shared__ float sm[];
    float* Qs = sm;
    float* Ks = Qs + 64 * QPAD;
    float* Vs = Ks + 64 * QPAD;
    float* Ps = Vs + 64 * VPAD;

    int qb = blockIdx.x, h = blockIdx.y, b = blockIdx.z;
    int tid = threadIdx.x;
    int lane = tid & 31, w = tid >> 5;
    int g = lane >> 2, tig = lane & 3;

    const size_t rs = 3 * Dq;
    const float* qbase = qkv + ((size_t)(b * Tq + qb * 64)) * rs + h * HDq;

    #pragma unroll
    for (int i = 0; i < 8; i++) {
        int f = tid + i * 128;
        int r = f >> 4, c4 = (f & 15) * 4;
        float4 v = *(const float4*)(qbase + (size_t)r * rs + c4);
        float* dst = Qs + r * QPAD + c4;
        dst[0] = round_tf(v.x * 0.125f);
        dst[1] = round_tf(v.y * 0.125f);
        dst[2] = round_tf(v.z * 0.125f);
        dst[3] = round_tf(v.w * 0.125f);
    }

    float oacc[8][4];
    #pragma unroll
    for (int ni = 0; ni < 8; ni++)
        #pragma unroll
        for (int c = 0; c < 4; c++) oacc[ni][c] = 0.0f;
    float mrow0 = -CUDART_INF_F, mrow1 = -CUDART_INF_F;
    float lrow0 = 0.0f, lrow1 = 0.0f;

    int rloc0 = w * 16 + g;
    int rloc1 = rloc0 + 8;

    for (int kt = 0; kt <= qb; kt++) {
        __syncthreads();
        const float* kbase = qkv + ((size_t)(b * Tq + kt * 64)) * rs + Dq + h * HDq;
        const float* vbase = kbase + Dq;
        #pragma unroll
        for (int i = 0; i < 8; i++) {
            int f = tid + i * 128;
            int r = f >> 4, c4 = (f & 15) * 4;
            float4 kv = *(const float4*)(kbase + (size_t)r * rs + c4);
            float4 vv = *(const float4*)(vbase + (size_t)r * rs + c4);
            float* kd = Ks + r * QPAD + c4;
            kd[0] = round_tf(kv.x); kd[1] = round_tf(kv.y);
            kd[2] = round_tf(kv.z); kd[3] = round_tf(kv.w);
            float* vd = Vs + r * VPAD + c4;
            vd[0] = round_tf(vv.x); vd[1] = round_tf(vv.y);
            vd[2] = round_tf(vv.z); vd[3] = round_tf(vv.w);
        }
        __syncthreads();

        float sacc[8][4];
        #pragma unroll
        for (int ni = 0; ni < 8; ni++)
            #pragma unroll
            for (int c = 0; c < 4; c++) sacc[ni][c] = 0.0f;
        #pragma unroll
        for (int ks = 0; ks < 8; ks++) {
            int k0 = ks * 8;
            unsigned a0 = __float_as_uint(Qs[rloc0 * QPAD + k0 + tig]);
            unsigned a1 = __float_as_uint(Qs[rloc1 * QPAD + k0 + tig]);
            unsigned a2 = __float_as_uint(Qs[rloc0 * QPAD + k0 + tig + 4]);
            unsigned a3 = __float_as_uint(Qs[rloc1 * QPAD + k0 + tig + 4]);
            #pragma unroll
            for (int ni = 0; ni < 8; ni++) {
                unsigned b0 = __float_as_uint(Ks[(ni * 8 + g) * QPAD + k0 + tig]);
                unsigned b1 = __float_as_uint(Ks[(ni * 8 + g) * QPAD + k0 + tig + 4]);
                mma_tf32(sacc[ni], a0, a1, a2, a3, b0, b1);
            }
        }

        if (kt == qb) {
            #pragma unroll
            for (int ni = 0; ni < 8; ni++) {
                int c0 = ni * 8 + 2 * tig, c1 = c0 + 1;
                if (c0 > rloc0) sacc[ni][0] = -CUDART_INF_F;
                if (c1 > rloc0) sacc[ni][1] = -CUDART_INF_F;
                if (c0 > rloc1) sacc[ni][2] = -CUDART_INF_F;
                if (c1 > rloc1) sacc[ni][3] = -CUDART_INF_F;
            }
        }

        float mx0 = -CUDART_INF_F, mx1 = -CUDART_INF_F;
        #pragma unroll
        for (int ni = 0; ni < 8; ni++) {
            mx0 = fmaxf(mx0, fmaxf(sacc[ni][0], sacc[ni][1]));
            mx1 = fmaxf(mx1, fmaxf(sacc[ni][2], sacc[ni][3]));
        }
        mx0 = fmaxf(mx0, __shfl_xor_sync(0xffffffffu, mx0, 1));
        mx0 = fmaxf(mx0, __shfl_xor_sync(0xffffffffu, mx0, 2));
        mx1 = fmaxf(mx1, __shfl_xor_sync(0xffffffffu, mx1, 1));
        mx1 = fmaxf(mx1, __shfl_xor_sync(0xffffffffu, mx1, 2));

        float mn0 = fmaxf(mrow0, mx0);
        float mn1 = fmaxf(mrow1, mx1);
        float corr0 = __expf(mrow0 - mn0);
        float corr1 = __expf(mrow1 - mn1);

        float rs0 = 0.0f, rs1 = 0.0f;
        #pragma unroll
        for (int ni = 0; ni < 8; ni++) {
            float p00 = round_tf(__expf(sacc[ni][0] - mn0));
            float p01 = round_tf(__expf(sacc[ni][1] - mn0));
            float p10 = round_tf(__expf(sacc[ni][2] - mn1));
            float p11 = round_tf(__expf(sacc[ni][3] - mn1));
            rs0 += p00 + p01;
            rs1 += p10 + p11;
            int c0 = ni * 8 + 2 * tig;
            *(float2*)&Ps[rloc0 * QPAD + c0] = make_float2(p00, p01);
            *(float2*)&Ps[rloc1 * QPAD + c0] = make_float2(p10, p11);
        }
        rs0 += __shfl_xor_sync(0xffffffffu, rs0, 1);
        rs0 += __shfl_xor_sync(0xffffffffu, rs0, 2);
        rs1 += __shfl_xor_sync(0xffffffffu, rs1, 1);
        rs1 += __shfl_xor_sync(0xffffffffu, rs1, 2);

        lrow0 = lrow0 * corr0 + rs0;
        lrow1 = lrow1 * corr1 + rs1;
        mrow0 = mn0; mrow1 = mn1;

        #pragma unroll
        for (int ni = 0; ni < 8; ni++) {
            oacc[ni][0] *= corr0; oacc[ni][1] *= corr0;
            oacc[ni][2] *= corr1; oacc[ni][3] *= corr1;
        }
        __syncwarp();

        #pragma unroll
        for (int ks = 0; ks < 8; ks++) {
            int k0 = ks * 8;
            unsigned a0 = __float_as_uint(Ps[rloc0 * QPAD + k0 + tig]);
            unsigned a1 = __float_as_uint(Ps[rloc1 * QPAD + k0 + tig]);
            unsigned a2 = __float_as_uint(Ps[rloc0 * QPAD + k0 + tig + 4]);
            unsigned a3 = __float_as_uint(Ps[rloc1 * QPAD + k0 + tig + 4]);
            #pragma unroll
            for (int ni = 0; ni < 8; ni++) {
                unsigned b0 = __float_as_uint(Vs[(k0 + tig)     * VPAD + ni * 8 + g]);
                unsigned b1 = __float_as_uint(Vs[(k0 + tig + 4) * VPAD + ni * 8 + g]);
                mma_tf32(oacc[ni], a0, a1, a2, a3, b0, b1);
            }
        }
        __syncwarp();
    }

    float inv0 = 1.0f / lrow0;
    float inv1 = 1.0f / lrow1;
    size_t row0 = (size_t)(b * Tq + qb * 64 + rloc0);
    size_t row1 = row0 + 8;
    #pragma unroll
    for (int ni = 0; ni < 8; ni++) {
        int col = h * HDq + ni * 8 + 2 * tig;
        *(float2*)&y[row0 * Dq + col] = make_float2(
            round_tf(oacc[ni][0] * inv0), round_tf(oacc[ni][1] * inv0));
        *(float2*)&y[row1 * Dq + col] = make_float2(
            round_tf(oacc[ni][2] * inv1), round_tf(oacc[ni][3] * inv1));
    }
}

// ---------------------------------------------------------------------------
// Launch
// ---------------------------------------------------------------------------
extern "C" void kernel_launch(void* const* d_in, const int* in_sizes, int n_in,
                              void* d_out, int out_size) {
    const int*   idx     = (const int*)  d_in[0];
    const float* tok_emb = (const float*)d_in[1];
    const float* ln1_s   = (const float*)d_in[2];
    const float* ln1_b   = (const float*)d_in[3];
    const float* qkv_w   = (const float*)d_in[4];
    const float* qkv_b   = (const float*)d_in[5];
    const float* out_w   = (const float*)d_in[6];
    const float* out_b   = (const float*)d_in[7];
    const float* ln2_s   = (const float*)d_in[8];
    const float* ln2_b   = (const float*)d_in[9];
    const float* mlp_w1  = (const float*)d_in[10];
    const float* mlp_b1  = (const float*)d_in[11];
    const float* mlp_w2  = (const float*)d_in[12];
    const float* mlp_b2  = (const float*)d_in[13];
    const float* lnf_s   = (const float*)d_in[14];
    const float* lnf_b   = (const float*)d_in[15];
    const float* head_w  = (const float*)d_in[16];
    float* logits = (float*)d_out;

    float *x, *ln, *qkv, *y, *ff;
    float *wqkv, *wout, *wm1, *wm2, *whd;
    cudaGetSymbolAddress((void**)&x,    g_x);
    cudaGetSymbolAddress((void**)&ln,   g_ln);
    cudaGetSymbolAddress((void**)&qkv,  g_qkv);
    cudaGetSymbolAddress((void**)&y,    g_y);
    cudaGetSymbolAddress((void**)&ff,   g_ff);
    cudaGetSymbolAddress((void**)&wqkv, g_wqkv);
    cudaGetSymbolAddress((void**)&wout, g_wout);
    cudaGetSymbolAddress((void**)&wm1,  g_wm1);
    cudaGetSymbolAddress((void**)&wm2,  g_wm2);
    cudaGetSymbolAddress((void**)&whd,  g_whd);

    const int smem_n = 2 * (128 * 32 + 32 * 128) * (int)sizeof(float);  // 64 KB
    const int smem_w = 2 * (128 * 32 + 32 * 256) * (int)sizeof(float);  // 96 KB
    cudaFuncSetAttribute((const void*)tgemm_kernel<0, 128, 128>,
                         cudaFuncAttributeMaxDynamicSharedMemorySize, smem_n);
    cudaFuncSetAttribute((const void*)tgemm_kernel<1, 128, 128>,
                         cudaFuncAttributeMaxDynamicSharedMemorySize, smem_n);
    cudaFuncSetAttribute((const void*)tgemm_kernel<0, 256, 256>,
                         cudaFuncAttributeMaxDynamicSharedMemorySize, smem_w);
    cudaFuncSetAttribute((const void*)tgemm_kernel<2, 256, 256>,
                         cudaFuncAttributeMaxDynamicSharedMemorySize, smem_w);
    const int attn_smem = (3 * 64 * QPAD + 64 * VPAD) * (int)sizeof(float);
    cudaFuncSetAttribute(attn3_kernel,
                         cudaFuncAttributeMaxDynamicSharedMemorySize, attn_smem);

    auto rnd = [](const float* src, float* dst, int n) {
        int n4 = n / 4;
        round4_kernel<<<(n4 + 255) / 256, 256>>>((const float4*)src, (float4*)dst, n4);
    };
    rnd(qkv_w,  wqkv, Lq * Dq * 3 * Dq);
    rnd(out_w,  wout, Lq * Dq * Dq);
    rnd(mlp_w1, wm1,  Lq * Dq * FFq);
    rnd(mlp_w2, wm2,  Lq * FFq * Dq);
    rnd(head_w, whd,  Dq * Vq);

    embed_kernel<<<Rq, 256>>>(idx, tok_emb, x);

    for (int l = 0; l < Lq; l++) {
        ln_kernel<<<Rq, 256>>>(x, ln1_s + (size_t)l * Dq, ln1_b + (size_t)l * Dq, ln);
        // qkv: N=3072 — narrow (384 CTAs, good occupancy)
        tgemm_kernel<0, 128, 128><<<dim3(3 * Dq / 128, Rq / 128), 128, smem_n>>>(
            ln, wqkv + (size_t)l * Dq * 3 * Dq, qkv_b + (size_t)l * 3 * Dq,
            qkv, Rq, 3 * Dq, Dq);
        attn3_kernel<<<dim3(Tq / 64, Hq, Bq), 128, attn_smem>>>(qkv, y);
        // out-proj: N=1024 — narrow (wide would strand SMs)
        tgemm_kernel<1, 128, 128><<<dim3(Dq / 128, Rq / 128), 128, smem_n>>>(
            y, wout + (size_t)l * Dq * Dq, out_b + (size_t)l * Dq,
            x, Rq, Dq, Dq);
        ln_kernel<<<Rq, 256>>>(x, ln2_s + (size_t)l * Dq, ln2_b + (size_t)l * Dq, ln);
        // mlp1: N=4096 — wide (halves A-panel traffic)
        tgemm_kernel<2, 256, 256><<<dim3(FFq / 256, Rq / 128), 256, smem_w>>>(
            ln, wm1 + (size_t)l * Dq * FFq, mlp_b1 + (size_t)l * FFq,
            ff, Rq, FFq, Dq);
        // mlp2: N=1024 — narrow
        tgemm_kernel<1, 128, 128><<<dim3(Dq / 128, Rq / 128), 128, smem_n>>>(
            ff, wm2 + (size_t)l * FFq * Dq, mlp_b2 + (size_t)l * Dq,
            x, Rq, Dq, FFq);
    }

    ln_kernel<<<Rq, 256>>>(x, lnf_s, lnf_b, ln);
    // head: N=32000 — wide (A-panel reads 2 GB -> 1 GB)
    tgemm_kernel<0, 256, 256><<<dim3(Vq / 256, Rq / 128), 256, smem_w>>>(
        ln, whd, (const float*)nullptr, logits, Rq, Vq, Dq);
}

// round 9
// speedup vs baseline: 1.0489x; 1.0489x over previous
#include <cuda_runtime.h>
#include <math.h>
#include <math_constants.h>

// Problem constants
#define Bq  2
#define Tq  1024
#define Dq  1024
#define Hq  16
#define FFq 4096
#define Lq  8
#define Vq  32000
#define HDq 64
#define Rq  (Bq * Tq)   // 2048 rows

// ---------------------------------------------------------------------------
// Scratch (device globals; no runtime allocation allowed)
// ---------------------------------------------------------------------------
__device__ float g_x  [Rq * Dq];
__device__ float g_ln [Rq * Dq];
__device__ float g_qkv[Rq * 3 * Dq];
__device__ float g_y  [Rq * Dq];
__device__ float g_ff [Rq * FFq];

// tf32-rounded weight copies
__device__ float g_wqkv[Lq * Dq * 3 * Dq];
__device__ float g_wout[Lq * Dq * Dq];
__device__ float g_wm1 [Lq * Dq * FFq];
__device__ float g_wm2 [Lq * FFq * Dq];
__device__ float g_whd [Dq * Vq];

// ---------------------------------------------------------------------------
__device__ __forceinline__ unsigned f2tf(float x) {
    unsigned r;
    asm("cvt.rna.tf32.f32 %0, %1;" : "=r"(r) : "f"(x));
    return r;
}
__device__ __forceinline__ float round_tf(float x) {
    return __uint_as_float(f2tf(x));
}

__global__ void round4_kernel(const float4* __restrict__ in,
                              float4* __restrict__ out, int n4) {
    int i = blockIdx.x * blockDim.x + threadIdx.x;
    if (i < n4) {
        float4 v = in[i];
        out[i] = make_float4(round_tf(v.x), round_tf(v.y),
                             round_tf(v.z), round_tf(v.w));
    }
}

// ---------------------------------------------------------------------------
__device__ __forceinline__ float block_sum(float v, float* sh) {
    int lane = threadIdx.x & 31, w = threadIdx.x >> 5, nw = blockDim.x >> 5;
    #pragma unroll
    for (int o = 16; o; o >>= 1) v += __shfl_xor_sync(0xffffffffu, v, o);
    if (lane == 0) sh[w] = v;
    __syncthreads();
    if (w == 0) {
        v = (lane < nw) ? sh[lane] : 0.0f;
        #pragma unroll
        for (int o = 16; o; o >>= 1) v += __shfl_xor_sync(0xffffffffu, v, o);
        if (lane == 0) sh[0] = v;
    }
    __syncthreads();
    float r = sh[0];
    __syncthreads();
    return r;
}

// ---------------------------------------------------------------------------
__global__ void embed_kernel(const int* __restrict__ idx,
                             const float* __restrict__ emb,
                             float* __restrict__ x) {
    int row = blockIdx.x;
    int t   = row % Tq;
    int tok = idx[row];
    const float* er = emb + (size_t)tok * Dq;
    const float neg_log = -logf(10000.0f) / (float)Dq;
    for (int d = threadIdx.x; d < Dq; d += blockDim.x) {
        int i2 = d & ~1;
        float freq = expf(neg_log * (float)i2);
        float ang  = (float)t * freq;
        float pe   = (d & 1) ? cosf(ang) : sinf(ang);
        x[(size_t)row * Dq + d] = er[d] + pe;
    }
}

// ---------------------------------------------------------------------------
__global__ void ln_kernel(const float* __restrict__ x,
                          const float* __restrict__ sc,
                          const float* __restrict__ bi,
                          float* __restrict__ out) {
    __shared__ float sh[32];
    int row = blockIdx.x;
    const float* xr = x + (size_t)row * Dq;
    float v[4];
    float lsum = 0.0f;
    #pragma unroll
    for (int i = 0; i < 4; i++) {
        v[i] = xr[threadIdx.x + i * 256];
        lsum += v[i];
    }
    float mean = block_sum(lsum, sh) * (1.0f / (float)Dq);
    float lsq = 0.0f;
    #pragma unroll
    for (int i = 0; i < 4; i++) {
        float d = v[i] - mean;
        lsq += d * d;
    }
    float var = block_sum(lsq, sh) * (1.0f / (float)Dq);
    float inv = rsqrtf(var + 1e-5f);
    #pragma unroll
    for (int i = 0; i < 4; i++) {
        int d = threadIdx.x + i * 256;
        out[(size_t)row * Dq + d] = round_tf((v[i] - mean) * inv * sc[d] + bi[d]);
    }
}

// ---------------------------------------------------------------------------
// TF32 tensor-core GEMM, 3-stage cp.async ring, 128 threads, BN=128.
// Template over BMt: 128 (big GEMMs, warp tile 64x64) or 64 (small GEMMs,
// warp tile 32x64, 3 CTAs/SM for M=2048/N=1024 shapes).
// Always-commit keeps cp.async group accounting exact for wait_group 1.
// ---------------------------------------------------------------------------
__device__ __forceinline__ void mma_tf32(float c[4],
                                         unsigned a0, unsigned a1, unsigned a2, unsigned a3,
                                         unsigned b0, unsigned b1) {
    asm volatile(
        "mma.sync.aligned.m16n8k8.row.col.f32.tf32.tf32.f32 "
        "{%0,%1,%2,%3}, {%4,%5,%6,%7}, {%8,%9}, {%0,%1,%2,%3};"
        : "+f"(c[0]), "+f"(c[1]), "+f"(c[2]), "+f"(c[3])
        : "r"(a0), "r"(a1), "r"(a2), "r"(a3), "r"(b0), "r"(b1));
}

#define CP16(dst, src) \
    asm volatile("cp.async.cg.shared.global [%0], [%1], 16;\n" :: "r"(dst), "l"(src))

template <int EPI, int BMt>
__global__ __launch_bounds__(128)
void tgemm_kernel(const float* __restrict__ A, const float* __restrict__ B,
                  const float* __restrict__ bias, float* __restrict__ C,
                  int M, int N, int K) {
    constexpr int BN = 128, BK = 32, NT = 128;
    constexpr int ASZ = BMt * BK;
    constexpr int BSZ = BK * BN;
    constexpr int MI  = BMt / 32;       // 4 for BMt=128, 2 for BMt=64
    constexpr int IT_A = BMt / 16;      // A float4 loads per thread
    extern __shared__ float smf[];

    int tid  = threadIdx.x;
    int lane = tid & 31;
    int warp = tid >> 5;
    int g    = lane >> 2;
    int tig  = lane & 3;
    int wm   = warp & 1;
    int wn   = warp >> 1;
    int rm   = wm * (BMt / 2);
    int cn   = wn * 64;
    unsigned xora = (unsigned)(g << 2);
    unsigned xorb = (unsigned)(tig << 3);

    const float* Ab = A + (size_t)(blockIdx.y * BMt) * K;
    const float* Bb = B + (size_t)(blockIdx.x) * BN;

    float acc[MI][8][4];
    #pragma unroll
    for (int mi = 0; mi < MI; mi++)
        #pragma unroll
        for (int ni = 0; ni < 8; ni++)
            #pragma unroll
            for (int c = 0; c < 4; c++) acc[mi][ni][c] = 0.0f;

    int a_m  = tid >> 3;                // 0..15
    int a_k4 = (tid & 7) << 2;
    int b_k  = tid >> 5;                // 0..3
    int b_n4 = (tid & 31) << 2;
    unsigned xsta = (unsigned)((a_m & 7) << 2);
    unsigned xstb = (unsigned)((b_k & 3) << 3);

    unsigned sBase = (unsigned)__cvta_generic_to_shared(smf);

    auto issue = [&](int kt, int p) {
        unsigned sa = sBase + (unsigned)(p * (ASZ + BSZ)) * 4u;
        unsigned sb = sa + (unsigned)ASZ * 4u;
        #pragma unroll
        for (int i = 0; i < IT_A; i++) {
            int m = i * 16 + a_m;
            const float* src = Ab + (size_t)m * K + kt + a_k4;
            unsigned dst = sa + (unsigned)(m * 32 + ((unsigned)a_k4 ^ xsta)) * 4u;
            CP16(dst, src);
        }
        #pragma unroll
        for (int i = 0; i < 8; i++) {
            int k = i * 4 + b_k;
            const float* src = Bb + (size_t)(kt + k) * N + b_n4;
            unsigned dst = sb + (unsigned)(k * BN + ((unsigned)b_n4 ^ xstb)) * 4u;
            CP16(dst, src);
        }
        asm volatile("cp.async.commit_group;\n");
    };

    int ntiles = K / BK;   // >= 32 for all our shapes
    issue(0, 0);
    issue(BK, 1);

    for (int t = 0; t < ntiles; t++) {
        int p = t % 3;
        asm volatile("cp.async.wait_group 1;\n");
        __syncthreads();
        // keep exactly one group committed per iteration (may be empty)
        if (t + 2 < ntiles) {
            issue((t + 2) * BK, (t + 2) % 3);
        } else {
            asm volatile("cp.async.commit_group;\n");
        }

        const float* Ap = smf + p * (ASZ + BSZ);
        const float* Bp = Ap + ASZ;
        #pragma unroll
        for (int ks = 0; ks < 4; ks++) {
            int k0 = ks * 8;
            unsigned af[MI][4], bf[8][2];
            unsigned ka0 = (unsigned)(k0 + tig)     ^ xora;
            unsigned ka1 = (unsigned)(k0 + tig + 4) ^ xora;
            #pragma unroll
            for (int mi = 0; mi < MI; mi++) {
                int m1 = rm + mi * 16 + g;
                int m2 = m1 + 8;
                af[mi][0] = __float_as_uint(Ap[m1 * 32 + ka0]);
                af[mi][1] = __float_as_uint(Ap[m2 * 32 + ka0]);
                af[mi][2] = __float_as_uint(Ap[m1 * 32 + ka1]);
                af[mi][3] = __float_as_uint(Ap[m2 * 32 + ka1]);
            }
            #pragma unroll
            for (int ni = 0; ni < 8; ni++) {
                unsigned nb = (unsigned)(cn + ni * 8 + g) ^ xorb;
                bf[ni][0] = __float_as_uint(Bp[(k0 + tig)     * BN + nb]);
                bf[ni][1] = __float_as_uint(Bp[(k0 + tig + 4) * BN + nb]);
            }
            #pragma unroll
            for (int mi = 0; mi < MI; mi++)
                #pragma unroll
                for (int ni = 0; ni < 8; ni++)
                    mma_tf32(acc[mi][ni],
                             af[mi][0], af[mi][1], af[mi][2], af[mi][3],
                             bf[ni][0], bf[ni][1]);
        }
        __syncthreads();
    }

    #pragma unroll
    for (int ni = 0; ni < 8; ni++) {
        int gc = blockIdx.x * BN + cn + ni * 8 + 2 * tig;
        float bv0 = bias ? bias[gc]     : 0.0f;
        float bv1 = bias ? bias[gc + 1] : 0.0f;
        #pragma unroll
        for (int mi = 0; mi < MI; mi++) {
            int gr1 = blockIdx.y * BMt + rm + mi * 16 + g;
            int gr2 = gr1 + 8;
            float v00 = acc[mi][ni][0] + bv0;
            float v01 = acc[mi][ni][1] + bv1;
            float v10 = acc[mi][ni][2] + bv0;
            float v11 = acc[mi][ni][3] + bv1;
            float* p1 = C + (size_t)gr1 * N + gc;
            float* p2 = C + (size_t)gr2 * N + gc;
            if (EPI == 0) {
                *(float2*)p1 = make_float2(v00, v01);
                *(float2*)p2 = make_float2(v10, v11);
            } else if (EPI == 1) {
                float2 o1 = *(const float2*)p1;
                float2 o2 = *(const float2*)p2;
                *(float2*)p1 = make_float2(o1.x + v00, o1.y + v01);
                *(float2*)p2 = make_float2(o2.x + v10, o2.y + v11);
            } else {
                const float is2 = 0.70710678118654752f;
                *(float2*)p1 = make_float2(
                    round_tf(0.5f * v00 * (1.0f + erff(v00 * is2))),
                    round_tf(0.5f * v01 * (1.0f + erff(v01 * is2))));
                *(float2*)p2 = make_float2(
                    round_tf(0.5f * v10 * (1.0f + erff(v10 * is2))),
                    round_tf(0.5f * v11 * (1.0f + erff(v11 * is2))));
            }
        }
    }
}

// ---------------------------------------------------------------------------
// Tensor-core flash attention (unchanged from R6 — proven).
// ---------------------------------------------------------------------------
#define QPAD 68
#define VPAD 72

__global__ __launch_bounds__(128)
void attn3_kernel(const float* __restrict__ qkv, float* __restrict__ y) {
    extern __shared__ float sm[];
    float* Qs = sm;
    float* Ks = Qs + 64 * QPAD;
    float* Vs = Ks + 64 * QPAD;
    float* Ps = Vs + 64 * VPAD;

    int qb = blockIdx.x, h = blockIdx.y, b = blockIdx.z;
    int tid = threadIdx.x;
    int lane = tid & 31, w = tid >> 5;
    int g = lane >> 2, tig = lane & 3;

    const size_t rs = 3 * Dq;
    const float* qbase = qkv + ((size_t)(b * Tq + qb * 64)) * rs + h * HDq;

    #pragma unroll
    for (int i = 0; i < 8; i++) {
        int f = tid + i * 128;
        int r = f >> 4, c4 = (f & 15) * 4;
        float4 v = *(const float4*)(qbase + (size_t)r * rs + c4);
        float* dst = Qs + r * QPAD + c4;
        dst[0] = round_tf(v.x * 0.125f);
        dst[1] = round_tf(v.y * 0.125f);
        dst[2] = round_tf(v.z * 0.125f);
        dst[3] = round_tf(v.w * 0.125f);
    }

    float oacc[8][4];
    #pragma unroll
    for (int ni = 0; ni < 8; ni++)
        #pragma unroll
        for (int c = 0; c < 4; c++) oacc[ni][c] = 0.0f;
    float mrow0 = -CUDART_INF_F, mrow1 = -CUDART_INF_F;
    float lrow0 = 0.0f, lrow1 = 0.0f;

    int rloc0 = w * 16 + g;
    int rloc1 = rloc0 + 8;

    for (int kt = 0; kt <= qb; kt++) {
        __syncthreads();
        const float* kbase = qkv + ((size_t)(b * Tq + kt * 64)) * rs + Dq + h * HDq;
        const float* vbase = kbase + Dq;
        #pragma unroll
        for (int i = 0; i < 8; i++) {
            int f = tid + i * 128;
            int r = f >> 4, c4 = (f & 15) * 4;
            float4 kv = *(const float4*)(kbase + (size_t)r * rs + c4);
            float4 vv = *(const float4*)(vbase + (size_t)r * rs + c4);
            float* kd = Ks + r * QPAD + c4;
            kd[0] = round_tf(kv.x); kd[1] = round_tf(kv.y);
            kd[2] = round_tf(kv.z); kd[3] = round_tf(kv.w);
            float* vd = Vs + r * VPAD + c4;
            vd[0] = round_tf(vv.x); vd[1] = round_tf(vv.y);
            vd[2] = round_tf(vv.z); vd[3] = round_tf(vv.w);
        }
        __syncthreads();

        float sacc[8][4];
        #pragma unroll
        for (int ni = 0; ni < 8; ni++)
            #pragma unroll
            for (int c = 0; c < 4; c++) sacc[ni][c] = 0.0f;
        #pragma unroll
        for (int ks = 0; ks < 8; ks++) {
            int k0 = ks * 8;
            unsigned a0 = __float_as_uint(Qs[rloc0 * QPAD + k0 + tig]);
            unsigned a1 = __float_as_uint(Qs[rloc1 * QPAD + k0 + tig]);
            unsigned a2 = __float_as_uint(Qs[rloc0 * QPAD + k0 + tig + 4]);
            unsigned a3 = __float_as_uint(Qs[rloc1 * QPAD + k0 + tig + 4]);
            #pragma unroll
            for (int ni = 0; ni < 8; ni++) {
                unsigned b0 = __float_as_uint(Ks[(ni * 8 + g) * QPAD + k0 + tig]);
                unsigned b1 = __float_as_uint(Ks[(ni * 8 + g) * QPAD + k0 + tig + 4]);
                mma_tf32(sacc[ni], a0, a1, a2, a3, b0, b1);
            }
        }

        if (kt == qb) {
            #pragma unroll
            for (int ni = 0; ni < 8; ni++) {
                int c0 = ni * 8 + 2 * tig, c1 = c0 + 1;
                if (c0 > rloc0) sacc[ni][0] = -CUDART_INF_F;
                if (c1 > rloc0) sacc[ni][1] = -CUDART_INF_F;
                if (c0 > rloc1) sacc[ni][2] = -CUDART_INF_F;
                if (c1 > rloc1) sacc[ni][3] = -CUDART_INF_F;
            }
        }

        float mx0 = -CUDART_INF_F, mx1 = -CUDART_INF_F;
        #pragma unroll
        for (int ni = 0; ni < 8; ni++) {
            mx0 = fmaxf(mx0, fmaxf(sacc[ni][0], sacc[ni][1]));
            mx1 = fmaxf(mx1, fmaxf(sacc[ni][2], sacc[ni][3]));
        }
        mx0 = fmaxf(mx0, __shfl_xor_sync(0xffffffffu, mx0, 1));
        mx0 = fmaxf(mx0, __shfl_xor_sync(0xffffffffu, mx0, 2));
        mx1 = fmaxf(mx1, __shfl_xor_sync(0xffffffffu, mx1, 1));
        mx1 = fmaxf(mx1, __shfl_xor_sync(0xffffffffu, mx1, 2));

        float mn0 = fmaxf(mrow0, mx0);
        float mn1 = fmaxf(mrow1, mx1);
        float corr0 = __expf(mrow0 - mn0);
        float corr1 = __expf(mrow1 - mn1);

        float rs0 = 0.0f, rs1 = 0.0f;
        #pragma unroll
        for (int ni = 0; ni < 8; ni++) {
            float p00 = round_tf(__expf(sacc[ni][0] - mn0));
            float p01 = round_tf(__expf(sacc[ni][1] - mn0));
            float p10 = round_tf(__expf(sacc[ni][2] - mn1));
            float p11 = round_tf(__expf(sacc[ni][3] - mn1));
            rs0 += p00 + p01;
            rs1 += p10 + p11;
            int c0 = ni * 8 + 2 * tig;
            *(float2*)&Ps[rloc0 * QPAD + c0] = make_float2(p00, p01);
            *(float2*)&Ps[rloc1 * QPAD + c0] = make_float2(p10, p11);
        }
        rs0 += __shfl_xor_sync(0xffffffffu, rs0, 1);
        rs0 += __shfl_xor_sync(0xffffffffu, rs0, 2);
        rs1 += __shfl_xor_sync(0xffffffffu, rs1, 1);
        rs1 += __shfl_xor_sync(0xffffffffu, rs1, 2);

        lrow0 = lrow0 * corr0 + rs0;
        lrow1 = lrow1 * corr1 + rs1;
        mrow0 = mn0; mrow1 = mn1;

        #pragma unroll
        for (int ni = 0; ni < 8; ni++) {
            oacc[ni][0] *= corr0; oacc[ni][1] *= corr0;
            oacc[ni][2] *= corr1; oacc[ni][3] *= corr1;
        }
        __syncwarp();

        #pragma unroll
        for (int ks = 0; ks < 8; ks++) {
            int k0 = ks * 8;
            unsigned a0 = __float_as_uint(Ps[rloc0 * QPAD + k0 + tig]);
            unsigned a1 = __float_as_uint(Ps[rloc1 * QPAD + k0 + tig]);
            unsigned a2 = __float_as_uint(Ps[rloc0 * QPAD + k0 + tig + 4]);
            unsigned a3 = __float_as_uint(Ps[rloc1 * QPAD + k0 + tig + 4]);
            #pragma unroll
            for (int ni = 0; ni < 8; ni++) {
                unsigned b0 = __float_as_uint(Vs[(k0 + tig)     * VPAD + ni * 8 + g]);
                unsigned b1 = __float_as_uint(Vs[(k0 + tig + 4) * VPAD + ni * 8 + g]);
                mma_tf32(oacc[ni], a0, a1, a2, a3, b0, b1);
            }
        }
        __syncwarp();
    }

    float inv0 = 1.0f / lrow0;
    float inv1 = 1.0f / lrow1;
    size_t row0 = (size_t)(b * Tq + qb * 64 + rloc0);
    size_t row1 = row0 + 8;
    #pragma unroll
    for (int ni = 0; ni < 8; ni++) {
        int col = h * HDq + ni * 8 + 2 * tig;
        *(float2*)&y[row0 * Dq + col] = make_float2(
            round_tf(oacc[ni][0] * inv0), round_tf(oacc[ni][1] * inv0));
        *(float2*)&y[row1 * Dq + col] = make_float2(
            round_tf(oacc[ni][2] * inv1), round_tf(oacc[ni][3] * inv1));
    }
}

// ---------------------------------------------------------------------------
// Launch
// ---------------------------------------------------------------------------
extern "C" void kernel_launch(void* const* d_in, const int* in_sizes, int n_in,
                              void* d_out, int out_size) {
    const int*   idx     = (const int*)  d_in[0];
    const float* tok_emb = (const float*)d_in[1];
    const float* ln1_s   = (const float*)d_in[2];
    const float* ln1_b   = (const float*)d_in[3];
    const float* qkv_w   = (const float*)d_in[4];
    const float* qkv_b   = (const float*)d_in[5];
    const float* out_w   = (const float*)d_in[6];
    const float* out_b   = (const float*)d_in[7];
    const float* ln2_s   = (const float*)d_in[8];
    const float* ln2_b   = (const float*)d_in[9];
    const float* mlp_w1  = (const float*)d_in[10];
    const float* mlp_b1  = (const float*)d_in[11];
    const float* mlp_w2  = (const float*)d_in[12];
    const float* mlp_b2  = (const float*)d_in[13];
    const float* lnf_s   = (const float*)d_in[14];
    const float* lnf_b   = (const float*)d_in[15];
    const float* head_w  = (const float*)d_in[16];
    float* logits = (float*)d_out;

    float *x, *ln, *qkv, *y, *ff;
    float *wqkv, *wout, *wm1, *wm2, *whd;
    cudaGetSymbolAddress((void**)&x,    g_x);
    cudaGetSymbolAddress((void**)&ln,   g_ln);
    cudaGetSymbolAddress((void**)&qkv,  g_qkv);
    cudaGetSymbolAddress((void**)&y,    g_y);
    cudaGetSymbolAddress((void**)&ff,   g_ff);
    cudaGetSymbolAddress((void**)&wqkv, g_wqkv);
    cudaGetSymbolAddress((void**)&wout, g_wout);
    cudaGetSymbolAddress((void**)&wm1,  g_wm1);
    cudaGetSymbolAddress((void**)&wm2,  g_wm2);
    cudaGetSymbolAddress((void**)&whd,  g_whd);

    // 3-stage smem: BMt=128 -> 3*(4096+4096)*4 = 96 KB ; BMt=64 -> 72 KB
    const int smem128 = 3 * (128 * 32 + 32 * 128) * (int)sizeof(float);
    const int smem64  = 3 * ( 64 * 32 + 32 * 128) * (int)sizeof(float);
    cudaFuncSetAttribute((const void*)tgemm_kernel<0, 128>,
                         cudaFuncAttributeMaxDynamicSharedMemorySize, smem128);
    cudaFuncSetAttribute((const void*)tgemm_kernel<2, 128>,
                         cudaFuncAttributeMaxDynamicSharedMemorySize, smem128);
    cudaFuncSetAttribute((const void*)tgemm_kernel<1, 64>,
                         cudaFuncAttributeMaxDynamicSharedMemorySize, smem64);
    const int attn_smem = (3 * 64 * QPAD + 64 * VPAD) * (int)sizeof(float);
    cudaFuncSetAttribute(attn3_kernel,
                         cudaFuncAttributeMaxDynamicSharedMemorySize, attn_smem);

    auto rnd = [](const float* src, float* dst, int n) {
        int n4 = n / 4;
        round4_kernel<<<(n4 + 255) / 256, 256>>>((const float4*)src, (float4*)dst, n4);
    };
    rnd(qkv_w,  wqkv, Lq * Dq * 3 * Dq);
    rnd(out_w,  wout, Lq * Dq * Dq);
    rnd(mlp_w1, wm1,  Lq * Dq * FFq);
    rnd(mlp_w2, wm2,  Lq * FFq * Dq);
    rnd(head_w, whd,  Dq * Vq);

    embed_kernel<<<Rq, 256>>>(idx, tok_emb, x);

    for (int l = 0; l < Lq; l++) {
        ln_kernel<<<Rq, 256>>>(x, ln1_s + (size_t)l * Dq, ln1_b + (size_t)l * Dq, ln);
        // qkv: N=3072, BMt=128 (384 CTAs)
        tgemm_kernel<0, 128><<<dim3(3 * Dq / 128, Rq / 128), 128, smem128>>>(
            ln, wqkv + (size_t)l * Dq * 3 * Dq, qkv_b + (size_t)l * 3 * Dq,
            qkv, Rq, 3 * Dq, Dq);
        attn3_kernel<<<dim3(Tq / 64, Hq, Bq), 128, attn_smem>>>(qkv, y);
        // out-proj: N=1024, BMt=64 (256 CTAs, 3 CTAs/SM)
        tgemm_kernel<1, 64><<<dim3(Dq / 128, Rq / 64), 128, smem64>>>(
            y, wout + (size_t)l * Dq * Dq, out_b + (size_t)l * Dq,
            x, Rq, Dq, Dq);
        ln_kernel<<<Rq, 256>>>(x, ln2_s + (size_t)l * Dq, ln2_b + (size_t)l * Dq, ln);
        // mlp1: N=4096, BMt=128 (512 CTAs)
        tgemm_kernel<2, 128><<<dim3(FFq / 128, Rq / 128), 128, smem128>>>(
            ln, wm1 + (size_t)l * Dq * FFq, mlp_b1 + (size_t)l * FFq,
            ff, Rq, FFq, Dq);
        // mlp2: N=1024, BMt=64 (256 CTAs)
        tgemm_kernel<1, 64><<<dim3(Dq / 128, Rq / 64), 128, smem64>>>(
            ff, wm2 + (size_t)l * FFq * Dq, mlp_b2 + (size_t)l * Dq,
            x, Rq, Dq, FFq);
    }

    ln_kernel<<<Rq, 256>>>(x, lnf_s, lnf_b, ln);
    // head: N=32000, BMt=128 (4000 CTAs)
    tgemm_kernel<0, 128><<<dim3(Vq / 128, Rq / 128), 128, smem128>>>(
        ln, whd, (const float*)nullptr, logits, Rq, Vq, Dq);
}

// round 10
// speedup vs baseline: 1.6118x; 1.5366x over previous
#include <cuda_runtime.h>
#include <cuda_fp16.h>
#include <math.h>
#include <math_constants.h>

// Problem constants
#define Bq  2
#define Tq  1024
#define Dq  1024
#define Hq  16
#define FFq 4096
#define Lq  8
#define Vq  32000
#define HDq 64
#define Rq  (Bq * Tq)   // 2048 rows

// ---------------------------------------------------------------------------
// Scratch (device globals; no runtime allocation allowed)
// ---------------------------------------------------------------------------
__device__ float  g_x  [Rq * Dq];       // residual stream (fp32)
__device__ float  g_qkv[Rq * 3 * Dq];   // q|k|v (fp32, attention input)
__device__ __half g_lnh[Rq * Dq];       // layernorm output (fp16 GEMM A)
__device__ __half g_yh [Rq * Dq];       // attention output (fp16 GEMM A)
__device__ __half g_ffh[Rq * FFq];      // mlp hidden (fp16 GEMM A)

// k-pair-interleaved half2 weights: [K/2][N], elem = (w[2k2][n], w[2k2+1][n])
__device__ __half2 g_wqkv_h[Lq * (Dq/2) * 3 * Dq];
__device__ __half2 g_wout_h[Lq * (Dq/2) * Dq];
__device__ __half2 g_wm1_h [Lq * (Dq/2) * FFq];
__device__ __half2 g_wm2_h [Lq * (FFq/2) * Dq];
__device__ __half2 g_whd_h [(Dq/2) * Vq];

// ---------------------------------------------------------------------------
__device__ __forceinline__ unsigned f2tf(float x) {
    unsigned r;
    asm("cvt.rna.tf32.f32 %0, %1;" : "=r"(r) : "f"(x));
    return r;
}
__device__ __forceinline__ float round_tf(float x) {
    return __uint_as_float(f2tf(x));
}

// fp32 [K][N] (per-layer) -> half2 [K/2][N], blockIdx.y = layer
__global__ void w2h_kernel(const float* __restrict__ in,
                           __half2* __restrict__ out, int K, int N) {
    const float* inp = in + (size_t)blockIdx.y * K * N;
    __half2* outp = out + (size_t)blockIdx.y * (K / 2) * N;
    int i = blockIdx.x * blockDim.x + threadIdx.x;
    int total = (K / 2) * N;
    if (i < total) {
        int k2 = i / N, n = i - k2 * N;
        outp[i] = __floats2half2_rn(inp[(size_t)(2 * k2) * N + n],
                                    inp[(size_t)(2 * k2 + 1) * N + n]);
    }
}

// ---------------------------------------------------------------------------
__device__ __forceinline__ float block_sum(float v, float* sh) {
    int lane = threadIdx.x & 31, w = threadIdx.x >> 5, nw = blockDim.x >> 5;
    #pragma unroll
    for (int o = 16; o; o >>= 1) v += __shfl_xor_sync(0xffffffffu, v, o);
    if (lane == 0) sh[w] = v;
    __syncthreads();
    if (w == 0) {
        v = (lane < nw) ? sh[lane] : 0.0f;
        #pragma unroll
        for (int o = 16; o; o >>= 1) v += __shfl_xor_sync(0xffffffffu, v, o);
        if (lane == 0) sh[0] = v;
    }
    __syncthreads();
    float r = sh[0];
    __syncthreads();
    return r;
}

// ---------------------------------------------------------------------------
__global__ void embed_kernel(const int* __restrict__ idx,
                             const float* __restrict__ emb,
                             float* __restrict__ x) {
    int row = blockIdx.x;
    int t   = row % Tq;
    int tok = idx[row];
    const float* er = emb + (size_t)tok * Dq;
    const float neg_log = -logf(10000.0f) / (float)Dq;
    for (int d = threadIdx.x; d < Dq; d += blockDim.x) {
        int i2 = d & ~1;
        float freq = expf(neg_log * (float)i2);
        float ang  = (float)t * freq;
        float pe   = (d & 1) ? cosf(ang) : sinf(ang);
        x[(size_t)row * Dq + d] = er[d] + pe;
    }
}

// ---------------------------------------------------------------------------
// LayerNorm; writes fp16 (feeds GEMM A)
// ---------------------------------------------------------------------------
__global__ void ln_kernel(const float* __restrict__ x,
                          const float* __restrict__ sc,
                          const float* __restrict__ bi,
                          __half* __restrict__ out) {
    __shared__ float sh[32];
    int row = blockIdx.x;
    const float* xr = x + (size_t)row * Dq;
    float v[4];
    float lsum = 0.0f;
    #pragma unroll
    for (int i = 0; i < 4; i++) {
        v[i] = xr[threadIdx.x + i * 256];
        lsum += v[i];
    }
    float mean = block_sum(lsum, sh) * (1.0f / (float)Dq);
    float lsq = 0.0f;
    #pragma unroll
    for (int i = 0; i < 4; i++) {
        float d = v[i] - mean;
        lsq += d * d;
    }
    float var = block_sum(lsq, sh) * (1.0f / (float)Dq);
    float inv = rsqrtf(var + 1e-5f);
    #pragma unroll
    for (int i = 0; i < 4; i++) {
        int d = threadIdx.x + i * 256;
        out[(size_t)row * Dq + d] = __float2half_rn((v[i] - mean) * inv * sc[d] + bi[d]);
    }
}

// ---------------------------------------------------------------------------
// FP16 tensor-core GEMM (m16n8k16, fp32 accumulate), 3-stage cp.async ring.
// A: half [M][K] row-major. B: half2 k-pair-interleaved [K/2][N].
// BN=128, 128 threads, warp tile BMt/2 x 64. BMt in {128, 64}.
//   EPI 0: C(fp32) = AB + bias
//   EPI 1: C(fp32) += AB + bias
//   EPI 2: C(fp16) = gelu(AB + bias)
// A smem: [BMt][16] words (2 halves each), 16B-chunk swizzle c ^ ((m>>1)&3).
// B smem: [16][128] words (half2), word swizzle n ^ (8*(k2&3)).
// ---------------------------------------------------------------------------
__device__ __forceinline__ void mma_f16(float c[4],
                                        unsigned a0, unsigned a1, unsigned a2, unsigned a3,
                                        unsigned b0, unsigned b1) {
    asm volatile(
        "mma.sync.aligned.m16n8k16.row.col.f32.f16.f16.f32 "
        "{%0,%1,%2,%3}, {%4,%5,%6,%7}, {%8,%9}, {%0,%1,%2,%3};"
        : "+f"(c[0]), "+f"(c[1]), "+f"(c[2]), "+f"(c[3])
        : "r"(a0), "r"(a1), "r"(a2), "r"(a3), "r"(b0), "r"(b1));
}

#define CP16(dst, src) \
    asm volatile("cp.async.cg.shared.global [%0], [%1], 16;\n" :: "r"(dst), "l"(src))

template <int EPI, int BMt>
__global__ __launch_bounds__(128)
void hgemm_kernel(const __half* __restrict__ A, const __half2* __restrict__ B2,
                  const float* __restrict__ bias, float* __restrict__ C,
                  int M, int N, int K) {
    constexpr int BK = 32;                 // halves of K per tile
    constexpr int ASZW = BMt * 16;         // A words per stage (word = 2 halves)
    constexpr int BSZW = 16 * 128;         // B words per stage
    constexpr int STG  = ASZW + BSZW;
    constexpr int MI   = BMt / 32;
    extern __shared__ unsigned smw[];

    int tid  = threadIdx.x;
    int lane = tid & 31;
    int warp = tid >> 5;
    int g    = lane >> 2;
    int tig  = lane & 3;
    int wm   = warp & 1;
    int wn   = warp >> 1;
    int rm   = wm * (BMt / 2);
    int cn   = wn * 64;

    const __half*  Ab  = A + (size_t)(blockIdx.y * BMt) * K;
    const __half2* Bb2 = B2 + (size_t)blockIdx.x * 128;

    float acc[MI][8][4];
    #pragma unroll
    for (int mi = 0; mi < MI; mi++)
        #pragma unroll
        for (int ni = 0; ni < 8; ni++)
            #pragma unroll
            for (int c = 0; c < 4; c++) acc[mi][ni][c] = 0.0f;

    unsigned sBase = (unsigned)__cvta_generic_to_shared(smw);

    auto issue = [&](int kt, int p) {
        unsigned sa = sBase + (unsigned)(p * STG) * 4u;
        unsigned sb = sa + (unsigned)ASZW * 4u;
        // A: BMt rows x 4 chunks (16B = 8 halves)
        #pragma unroll
        for (int i = 0; i < BMt / 32; i++) {
            int lin = tid + i * 128;
            int m = lin >> 2, c = lin & 3;
            const __half* src = Ab + (size_t)m * K + kt + c * 8;
            unsigned dst = sa + (unsigned)(m * 16 + ((c ^ ((m >> 1) & 3)) << 2)) * 4u;
            CP16(dst, src);
        }
        // B: 16 k2-rows x 32 chunks (16B = 4 half2)
        #pragma unroll
        for (int i = 0; i < 4; i++) {
            int lin = tid + i * 128;
            int k2 = lin >> 5, c4 = lin & 31;
            const __half2* src = Bb2 + (size_t)(kt / 2 + k2) * N + c4 * 4;
            unsigned dst = sb + (unsigned)(k2 * 128 + ((c4 ^ (2 * (k2 & 3))) << 2)) * 4u;
            CP16(dst, src);
        }
        asm volatile("cp.async.commit_group;\n");
    };

    int ntiles = K / BK;
    issue(0, 0);
    issue(BK, 1);

    for (int t = 0; t < ntiles; t++) {
        int p = t % 3;
        asm volatile("cp.async.wait_group 1;\n");
        __syncthreads();
        if (t + 2 < ntiles) {
            issue((t + 2) * BK, (t + 2) % 3);
        } else {
            asm volatile("cp.async.commit_group;\n");
        }

        const unsigned* Ap = smw + p * STG;
        const unsigned* Bp = Ap + ASZW;
        #pragma unroll
        for (int ksi = 0; ksi < 2; ksi++) {
            // A logical words: tig + ksi*8 (chunk 2*ksi) and 4+tig+ksi*8 (chunk 2*ksi+1)
            unsigned af[MI][4], bf[8][2];
            #pragma unroll
            for (int mi = 0; mi < MI; mi++) {
                int m1 = rm + mi * 16 + g;
                int m2 = m1 + 8;
                unsigned s1 = (unsigned)((m1 >> 1) & 3);
                unsigned s2 = (unsigned)((m2 >> 1) & 3);
                unsigned c0 = (unsigned)(2 * ksi);
                af[mi][0] = Ap[m1 * 16 + (((c0    ) ^ s1) << 2) + tig];
                af[mi][1] = Ap[m2 * 16 + (((c0    ) ^ s2) << 2) + tig];
                af[mi][2] = Ap[m1 * 16 + (((c0 + 1) ^ s1) << 2) + tig];
                af[mi][3] = Ap[m2 * 16 + (((c0 + 1) ^ s2) << 2) + tig];
            }
            int k2b = ksi * 8;
            #pragma unroll
            for (int ni = 0; ni < 8; ni++) {
                unsigned nb = (unsigned)(cn + ni * 8 + g);
                bf[ni][0] = Bp[(k2b + tig)     * 128 + (nb ^ (unsigned)(8 * tig))];
                bf[ni][1] = Bp[(k2b + tig + 4) * 128 + (nb ^ (unsigned)(8 * tig))];
            }
            #pragma unroll
            for (int mi = 0; mi < MI; mi++)
                #pragma unroll
                for (int ni = 0; ni < 8; ni++)
                    mma_f16(acc[mi][ni],
                            af[mi][0], af[mi][1], af[mi][2], af[mi][3],
                            bf[ni][0], bf[ni][1]);
        }
        __syncthreads();
    }

    // ---- epilogue ----
    #pragma unroll
    for (int ni = 0; ni < 8; ni++) {
        int gc = blockIdx.x * 128 + cn + ni * 8 + 2 * tig;
        float bv0 = bias ? bias[gc]     : 0.0f;
        float bv1 = bias ? bias[gc + 1] : 0.0f;
        #pragma unroll
        for (int mi = 0; mi < MI; mi++) {
            int gr1 = blockIdx.y * BMt + rm + mi * 16 + g;
            int gr2 = gr1 + 8;
            float v00 = acc[mi][ni][0] + bv0;
            float v01 = acc[mi][ni][1] + bv1;
            float v10 = acc[mi][ni][2] + bv0;
            float v11 = acc[mi][ni][3] + bv1;
            if (EPI == 0) {
                *(float2*)(C + (size_t)gr1 * N + gc) = make_float2(v00, v01);
                *(float2*)(C + (size_t)gr2 * N + gc) = make_float2(v10, v11);
            } else if (EPI == 1) {
                float2* p1 = (float2*)(C + (size_t)gr1 * N + gc);
                float2* p2 = (float2*)(C + (size_t)gr2 * N + gc);
                float2 o1 = *p1, o2 = *p2;
                *p1 = make_float2(o1.x + v00, o1.y + v01);
                *p2 = make_float2(o2.x + v10, o2.y + v11);
            } else {
                const float is2 = 0.70710678118654752f;
                __half* Ch = (__half*)C;
                float g00 = 0.5f * v00 * (1.0f + erff(v00 * is2));
                float g01 = 0.5f * v01 * (1.0f + erff(v01 * is2));
                float g10 = 0.5f * v10 * (1.0f + erff(v10 * is2));
                float g11 = 0.5f * v11 * (1.0f + erff(v11 * is2));
                *(__half2*)(Ch + (size_t)gr1 * N + gc) = __floats2half2_rn(g00, g01);
                *(__half2*)(Ch + (size_t)gr2 * N + gc) = __floats2half2_rn(g10, g11);
            }
        }
    }
}

// ---------------------------------------------------------------------------
// Tensor-core flash attention (proven R6 tf32 path); y written as fp16.
// ---------------------------------------------------------------------------
#define QPAD 68
#define VPAD 72

__device__ __forceinline__ void mma_tf32(float c[4],
                                         unsigned a0, unsigned a1, unsigned a2, unsigned a3,
                                         unsigned b0, unsigned b1) {
    asm volatile(
        "mma.sync.aligned.m16n8k8.row.col.f32.tf32.tf32.f32 "
        "{%0,%1,%2,%3}, {%4,%5,%6,%7}, {%8,%9}, {%0,%1,%2,%3};"
        : "+f"(c[0]), "+f"(c[1]), "+f"(c[2]), "+f"(c[3])
        : "r"(a0), "r"(a1), "r"(a2), "r"(a3), "r"(b0), "r"(b1));
}

__global__ __launch_bounds__(128)
void attn3_kernel(const float* __restrict__ qkv, __half* __restrict__ y) {
    extern __shared__ float sm[];
    float* Qs = sm;
    float* Ks = Qs + 64 * QPAD;
    float* Vs = Ks + 64 * QPAD;
    float* Ps = Vs + 64 * VPAD;

    int qb = blockIdx.x, h = blockIdx.y, b = blockIdx.z;
    int tid = threadIdx.x;
    int lane = tid & 31, w = tid >> 5;
    int g = lane >> 2, tig = lane & 3;

    const size_t rs = 3 * Dq;
    const float* qbase = qkv + ((size_t)(b * Tq + qb * 64)) * rs + h * HDq;

    #pragma unroll
    for (int i = 0; i < 8; i++) {
        int f = tid + i * 128;
        int r = f >> 4, c4 = (f & 15) * 4;
        float4 v = *(const float4*)(qbase + (size_t)r * rs + c4);
        float* dst = Qs + r * QPAD + c4;
        dst[0] = round_tf(v.x * 0.125f);
        dst[1] = round_tf(v.y * 0.125f);
        dst[2] = round_tf(v.z * 0.125f);
        dst[3] = round_tf(v.w * 0.125f);
    }

    float oacc[8][4];
    #pragma unroll
    for (int ni = 0; ni < 8; ni++)
        #pragma unroll
        for (int c = 0; c < 4; c++) oacc[ni][c] = 0.0f;
    float mrow0 = -CUDART_INF_F, mrow1 = -CUDART_INF_F;
    float lrow0 = 0.0f, lrow1 = 0.0f;

    int rloc0 = w * 16 + g;
    int rloc1 = rloc0 + 8;

    for (int kt = 0; kt <= qb; kt++) {
        __syncthreads();
        const float* kbase = qkv + ((size_t)(b * Tq + kt * 64)) * rs + Dq + h * HDq;
        const float* vbase = kbase + Dq;
        #pragma unroll
        for (int i = 0; i < 8; i++) {
            int f = tid + i * 128;
            int r = f >> 4, c4 = (f & 15) * 4;
            float4 kv = *(const float4*)(kbase + (size_t)r * rs + c4);
            float4 vv = *(const float4*)(vbase + (size_t)r * rs + c4);
            float* kd = Ks + r * QPAD + c4;
            kd[0] = round_tf(kv.x); kd[1] = round_tf(kv.y);
            kd[2] = round_tf(kv.z); kd[3] = round_tf(kv.w);
            float* vd = Vs + r * VPAD + c4;
            vd[0] = round_tf(vv.x); vd[1] = round_tf(vv.y);
            vd[2] = round_tf(vv.z); vd[3] = round_tf(vv.w);
        }
        __syncthreads();

        float sacc[8][4];
        #pragma unroll
        for (int ni = 0; ni < 8; ni++)
            #pragma unroll
            for (int c = 0; c < 4; c++) sacc[ni][c] = 0.0f;
        #pragma unroll
        for (int ks = 0; ks < 8; ks++) {
            int k0 = ks * 8;
            unsigned a0 = __float_as_uint(Qs[rloc0 * QPAD + k0 + tig]);
            unsigned a1 = __float_as_uint(Qs[rloc1 * QPAD + k0 + tig]);
            unsigned a2 = __float_as_uint(Qs[rloc0 * QPAD + k0 + tig + 4]);
            unsigned a3 = __float_as_uint(Qs[rloc1 * QPAD + k0 + tig + 4]);
            #pragma unroll
            for (int ni = 0; ni < 8; ni++) {
                unsigned b0 = __float_as_uint(Ks[(ni * 8 + g) * QPAD + k0 + tig]);
                unsigned b1 = __float_as_uint(Ks[(ni * 8 + g) * QPAD + k0 + tig + 4]);
                mma_tf32(sacc[ni], a0, a1, a2, a3, b0, b1);
            }
        }

        if (kt == qb) {
            #pragma unroll
            for (int ni = 0; ni < 8; ni++) {
                int c0 = ni * 8 + 2 * tig, c1 = c0 + 1;
                if (c0 > rloc0) sacc[ni][0] = -CUDART_INF_F;
                if (c1 > rloc0) sacc[ni][1] = -CUDART_INF_F;
                if (c0 > rloc1) sacc[ni][2] = -CUDART_INF_F;
                if (c1 > rloc1) sacc[ni][3] = -CUDART_INF_F;
            }
        }

        float mx0 = -CUDART_INF_F, mx1 = -CUDART_INF_F;
        #pragma unroll
        for (int ni = 0; ni < 8; ni++) {
            mx0 = fmaxf(mx0, fmaxf(sacc[ni][0], sacc[ni][1]));
            mx1 = fmaxf(mx1, fmaxf(sacc[ni][2], sacc[ni][3]));
        }
        mx0 = fmaxf(mx0, __shfl_xor_sync(0xffffffffu, mx0, 1));
        mx0 = fmaxf(mx0, __shfl_xor_sync(0xffffffffu, mx0, 2));
        mx1 = fmaxf(mx1, __shfl_xor_sync(0xffffffffu, mx1, 1));
        mx1 = fmaxf(mx1, __shfl_xor_sync(0xffffffffu, mx1, 2));

        float mn0 = fmaxf(mrow0, mx0);
        float mn1 = fmaxf(mrow1, mx1);
        float corr0 = __expf(mrow0 - mn0);
        float corr1 = __expf(mrow1 - mn1);

        float rs0 = 0.0f, rs1 = 0.0f;
        #pragma unroll
        for (int ni = 0; ni < 8; ni++) {
            float p00 = round_tf(__expf(sacc[ni][0] - mn0));
            float p01 = round_tf(__expf(sacc[ni][1] - mn0));
            float p10 = round_tf(__expf(sacc[ni][2] - mn1));
            float p11 = round_tf(__expf(sacc[ni][3] - mn1));
            rs0 += p00 + p01;
            rs1 += p10 + p11;
            int c0 = ni * 8 + 2 * tig;
            *(float2*)&Ps[rloc0 * QPAD + c0] = make_float2(p00, p01);
            *(float2*)&Ps[rloc1 * QPAD + c0] = make_float2(p10, p11);
        }
        rs0 += __shfl_xor_sync(0xffffffffu, rs0, 1);
        rs0 += __shfl_xor_sync(0xffffffffu, rs0, 2);
        rs1 += __shfl_xor_sync(0xffffffffu, rs1, 1);
        rs1 += __shfl_xor_sync(0xffffffffu, rs1, 2);

        lrow0 = lrow0 * corr0 + rs0;
        lrow1 = lrow1 * corr1 + rs1;
        mrow0 = mn0; mrow1 = mn1;

        #pragma unroll
        for (int ni = 0; ni < 8; ni++) {
            oacc[ni][0] *= corr0; oacc[ni][1] *= corr0;
            oacc[ni][2] *= corr1; oacc[ni][3] *= corr1;
        }
        __syncwarp();

        #pragma unroll
        for (int ks = 0; ks < 8; ks++) {
            int k0 = ks * 8;
            unsigned a0 = __float_as_uint(Ps[rloc0 * QPAD + k0 + tig]);
            unsigned a1 = __float_as_uint(Ps[rloc1 * QPAD + k0 + tig]);
            unsigned a2 = __float_as_uint(Ps[rloc0 * QPAD + k0 + tig + 4]);
            unsigned a3 = __float_as_uint(Ps[rloc1 * QPAD + k0 + tig + 4]);
            #pragma unroll
            for (int ni = 0; ni < 8; ni++) {
                unsigned b0 = __float_as_uint(Vs[(k0 + tig)     * VPAD + ni * 8 + g]);
                unsigned b1 = __float_as_uint(Vs[(k0 + tig + 4) * VPAD + ni * 8 + g]);
                mma_tf32(oacc[ni], a0, a1, a2, a3, b0, b1);
            }
        }
        __syncwarp();
    }

    float inv0 = 1.0f / lrow0;
    float inv1 = 1.0f / lrow1;
    size_t row0 = (size_t)(b * Tq + qb * 64 + rloc0);
    size_t row1 = row0 + 8;
    #pragma unroll
    for (int ni = 0; ni < 8; ni++) {
        int col = h * HDq + ni * 8 + 2 * tig;
        *(__half2*)&y[row0 * Dq + col] =
            __floats2half2_rn(oacc[ni][0] * inv0, oacc[ni][1] * inv0);
        *(__half2*)&y[row1 * Dq + col] =
            __floats2half2_rn(oacc[ni][2] * inv1, oacc[ni][3] * inv1);
    }
}

// ---------------------------------------------------------------------------
// Launch
// ---------------------------------------------------------------------------
extern "C" void kernel_launch(void* const* d_in, const int* in_sizes, int n_in,
                              void* d_out, int out_size) {
    const int*   idx     = (const int*)  d_in[0];
    const float* tok_emb = (const float*)d_in[1];
    const float* ln1_s   = (const float*)d_in[2];
    const float* ln1_b   = (const float*)d_in[3];
    const float* qkv_w   = (const float*)d_in[4];
    const float* qkv_b   = (const float*)d_in[5];
    const float* out_w   = (const float*)d_in[6];
    const float* out_b   = (const float*)d_in[7];
    const float* ln2_s   = (const float*)d_in[8];
    const float* ln2_b   = (const float*)d_in[9];
    const float* mlp_w1  = (const float*)d_in[10];
    const float* mlp_b1  = (const float*)d_in[11];
    const float* mlp_w2  = (const float*)d_in[12];
    const float* mlp_b2  = (const float*)d_in[13];
    const float* lnf_s   = (const float*)d_in[14];
    const float* lnf_b   = (const float*)d_in[15];
    const float* head_w  = (const float*)d_in[16];
    float* logits = (float*)d_out;

    float *x, *qkv;
    __half *lnh, *yh, *ffh;
    __half2 *wqkv, *wout, *wm1, *wm2, *whd;
    cudaGetSymbolAddress((void**)&x,    g_x);
    cudaGetSymbolAddress((void**)&qkv,  g_qkv);
    cudaGetSymbolAddress((void**)&lnh,  g_lnh);
    cudaGetSymbolAddress((void**)&yh,   g_yh);
    cudaGetSymbolAddress((void**)&ffh,  g_ffh);
    cudaGetSymbolAddress((void**)&wqkv, g_wqkv_h);
    cudaGetSymbolAddress((void**)&wout, g_wout_h);
    cudaGetSymbolAddress((void**)&wm1,  g_wm1_h);
    cudaGetSymbolAddress((void**)&wm2,  g_wm2_h);
    cudaGetSymbolAddress((void**)&whd,  g_whd_h);

    // smem: BMt=128 -> 3*(2048+2048)*4 = 48 KB ; BMt=64 -> 36 KB
    const int smem128 = 3 * (128 * 16 + 16 * 128) * (int)sizeof(unsigned);
    const int smem64  = 3 * ( 64 * 16 + 16 * 128) * (int)sizeof(unsigned);
    cudaFuncSetAttribute((const void*)hgemm_kernel<0, 128>,
                         cudaFuncAttributeMaxDynamicSharedMemorySize, smem128);
    cudaFuncSetAttribute((const void*)hgemm_kernel<2, 128>,
                         cudaFuncAttributeMaxDynamicSharedMemorySize, smem128);
    cudaFuncSetAttribute((const void*)hgemm_kernel<1, 64>,
                         cudaFuncAttributeMaxDynamicSharedMemorySize, smem64);
    const int attn_smem = (3 * 64 * QPAD + 64 * VPAD) * (int)sizeof(float);
    cudaFuncSetAttribute(attn3_kernel,
                         cudaFuncAttributeMaxDynamicSharedMemorySize, attn_smem);

    // weight convert: fp32 [K][N] -> half2 [K/2][N], per layer via blockIdx.y
    auto cvt = [](const float* src, __half2* dst, int K, int N, int L) {
        int total = (K / 2) * N;
        w2h_kernel<<<dim3((total + 255) / 256, L), 256>>>(src, dst, K, N);
    };
    cvt(qkv_w,  wqkv, Dq,  3 * Dq, Lq);
    cvt(out_w,  wout, Dq,  Dq,     Lq);
    cvt(mlp_w1, wm1,  Dq,  FFq,    Lq);
    cvt(mlp_w2, wm2,  FFq, Dq,     Lq);
    cvt(head_w, whd,  Dq,  Vq,     1);

    embed_kernel<<<Rq, 256>>>(idx, tok_emb, x);

    for (int l = 0; l < Lq; l++) {
        ln_kernel<<<Rq, 256>>>(x, ln1_s + (size_t)l * Dq, ln1_b + (size_t)l * Dq, lnh);
        // qkv: N=3072
        hgemm_kernel<0, 128><<<dim3(3 * Dq / 128, Rq / 128), 128, smem128>>>(
            lnh, wqkv + (size_t)l * (Dq / 2) * 3 * Dq, qkv_b + (size_t)l * 3 * Dq,
            qkv, Rq, 3 * Dq, Dq);
        attn3_kernel<<<dim3(Tq / 64, Hq, Bq), 128, attn_smem>>>(qkv, yh);
        // out-proj: N=1024, BMt=64
        hgemm_kernel<1, 64><<<dim3(Dq / 128, Rq / 64), 128, smem64>>>(
            yh, wout + (size_t)l * (Dq / 2) * Dq, out_b + (size_t)l * Dq,
            x, Rq, Dq, Dq);
        ln_kernel<<<Rq, 256>>>(x, ln2_s + (size_t)l * Dq, ln2_b + (size_t)l * Dq, lnh);
        // mlp1: N=4096, gelu -> fp16 ff
        hgemm_kernel<2, 128><<<dim3(FFq / 128, Rq / 128), 128, smem128>>>(
            lnh, wm1 + (size_t)l * (Dq / 2) * FFq, mlp_b1 + (size_t)l * FFq,
            (float*)ffh, Rq, FFq, Dq);
        // mlp2: N=1024, K=4096, BMt=64
        hgemm_kernel<1, 64><<<dim3(Dq / 128, Rq / 64), 128, smem64>>>(
            ffh, wm2 + (size_t)l * (FFq / 2) * Dq, mlp_b2 + (size_t)l * Dq,
            x, Rq, Dq, FFq);
    }

    ln_kernel<<<Rq, 256>>>(x, lnf_s, lnf_b, lnh);
    // head: N=32000
    hgemm_kernel<0, 128><<<dim3(Vq / 128, Rq / 128), 128, smem128>>>(
        lnh, whd, (const float*)nullptr, logits, Rq, Vq, Dq);
}

// round 11
// speedup vs baseline: 1.7843x; 1.1070x over previous
#include <cuda_runtime.h>
#include <cuda_fp16.h>
#include <math.h>
#include <math_constants.h>

// Problem constants
#define Bq  2
#define Tq  1024
#define Dq  1024
#define Hq  16
#define FFq 4096
#define Lq  8
#define Vq  32000
#define HDq 64
#define Rq  (Bq * Tq)   // 2048 rows

// ---------------------------------------------------------------------------
// Scratch (device globals; no runtime allocation allowed)
// ---------------------------------------------------------------------------
__device__ float  g_x  [Rq * Dq];       // residual stream (fp32)
__device__ float  g_qkv[Rq * 3 * Dq];   // q|k|v (fp32, attention input)
__device__ __half g_lnh[Rq * Dq];       // layernorm output (fp16 GEMM A)
__device__ __half g_yh [Rq * Dq];       // attention output (fp16 GEMM A)
__device__ __half g_ffh[Rq * FFq];      // mlp hidden (fp16 GEMM A)

// k-pair-interleaved half2 weights: [K/2][N], elem = (w[2k2][n], w[2k2+1][n])
__device__ __half2 g_wqkv_h[Lq * (Dq/2) * 3 * Dq];
__device__ __half2 g_wout_h[Lq * (Dq/2) * Dq];
__device__ __half2 g_wm1_h [Lq * (Dq/2) * FFq];
__device__ __half2 g_wm2_h [Lq * (FFq/2) * Dq];
__device__ __half2 g_whd_h [(Dq/2) * Vq];

// ---------------------------------------------------------------------------
// Weight convert: fp32 [K][N] -> half2 [K/2][N], 3D grid (n4, k2, layer).
// ---------------------------------------------------------------------------
__global__ void w2h4_kernel(const float4* __restrict__ in,
                            uint4* __restrict__ out, int K, int N) {
    int n4 = blockIdx.x * blockDim.x + threadIdx.x;   // float4 column index
    int N4 = N >> 2;
    if (n4 >= N4) return;
    int k2 = blockIdx.y;
    size_t lbase = (size_t)blockIdx.z * K * N4;       // in float4 units
    float4 a = in[lbase + (size_t)(2 * k2)     * N4 + n4];
    float4 b = in[lbase + (size_t)(2 * k2 + 1) * N4 + n4];
    __half2 h0 = __floats2half2_rn(a.x, b.x);
    __half2 h1 = __floats2half2_rn(a.y, b.y);
    __half2 h2 = __floats2half2_rn(a.z, b.z);
    __half2 h3 = __floats2half2_rn(a.w, b.w);
    uint4 u;
    u.x = *(unsigned*)&h0; u.y = *(unsigned*)&h1;
    u.z = *(unsigned*)&h2; u.w = *(unsigned*)&h3;
    // out layout half2[K/2][N] -> uint4 index (k2*N + 4*n4)/4 = k2*N4 + n4
    out[(size_t)blockIdx.z * (K / 2) * N4 + (size_t)k2 * N4 + n4] = u;
}

// ---------------------------------------------------------------------------
__global__ void embed_kernel(const int* __restrict__ idx,
                             const float* __restrict__ emb,
                             float* __restrict__ x) {
    int row = blockIdx.x;
    int t   = row % Tq;
    int tok = idx[row];
    const float* er = emb + (size_t)tok * Dq;
    const float neg_log = -logf(10000.0f) / (float)Dq;
    for (int d = threadIdx.x; d < Dq; d += blockDim.x) {
        int i2 = d & ~1;
        float freq = expf(neg_log * (float)i2);
        float ang  = (float)t * freq;
        float pe   = (d & 1) ? cosf(ang) : sinf(ang);
        x[(size_t)row * Dq + d] = er[d] + pe;
    }
}

// ---------------------------------------------------------------------------
// Warp-per-row LayerNorm (no smem, shfl-only reductions); writes fp16.
// 256 threads = 8 warps = 8 rows per CTA; grid = Rq/8.
// ---------------------------------------------------------------------------
__global__ __launch_bounds__(256)
void ln_kernel(const float* __restrict__ x,
               const float* __restrict__ sc,
               const float* __restrict__ bi,
               __half* __restrict__ out) {
    int lane = threadIdx.x & 31;
    int w    = threadIdx.x >> 5;
    int row  = blockIdx.x * 8 + w;
    const float4* xr = (const float4*)(x + (size_t)row * Dq);

    float4 v[8];
    float s = 0.0f;
    #pragma unroll
    for (int i = 0; i < 8; i++) {
        v[i] = xr[lane + i * 32];
        s += v[i].x + v[i].y + v[i].z + v[i].w;
    }
    #pragma unroll
    for (int o = 16; o; o >>= 1) s += __shfl_xor_sync(0xffffffffu, s, o);
    float mean = s * (1.0f / (float)Dq);

    float q = 0.0f;
    #pragma unroll
    for (int i = 0; i < 8; i++) {
        float dx = v[i].x - mean, dy = v[i].y - mean;
        float dz = v[i].z - mean, dw = v[i].w - mean;
        q += dx * dx + dy * dy + dz * dz + dw * dw;
    }
    #pragma unroll
    for (int o = 16; o; o >>= 1) q += __shfl_xor_sync(0xffffffffu, q, o);
    float inv = rsqrtf(q * (1.0f / (float)Dq) + 1e-5f);

    #pragma unroll
    for (int i = 0; i < 8; i++) {
        int c = (lane + i * 32) * 4;
        float o0 = (v[i].x - mean) * inv * sc[c + 0] + bi[c + 0];
        float o1 = (v[i].y - mean) * inv * sc[c + 1] + bi[c + 1];
        float o2 = (v[i].z - mean) * inv * sc[c + 2] + bi[c + 2];
        float o3 = (v[i].w - mean) * inv * sc[c + 3] + bi[c + 3];
        __half2 h0 = __floats2half2_rn(o0, o1);
        __half2 h1 = __floats2half2_rn(o2, o3);
        uint2 u;
        u.x = *(unsigned*)&h0; u.y = *(unsigned*)&h1;
        *(uint2*)(out + (size_t)row * Dq + c) = u;
    }
}

// ---------------------------------------------------------------------------
// FP16 tensor-core GEMM (m16n8k16, fp32 accumulate), 3-stage cp.async ring.
// (unchanged from R9 — proven)
// ---------------------------------------------------------------------------
__device__ __forceinline__ void mma_f16(float c[4],
                                        unsigned a0, unsigned a1, unsigned a2, unsigned a3,
                                        unsigned b0, unsigned b1) {
    asm volatile(
        "mma.sync.aligned.m16n8k16.row.col.f32.f16.f16.f32 "
        "{%0,%1,%2,%3}, {%4,%5,%6,%7}, {%8,%9}, {%0,%1,%2,%3};"
        : "+f"(c[0]), "+f"(c[1]), "+f"(c[2]), "+f"(c[3])
        : "r"(a0), "r"(a1), "r"(a2), "r"(a3), "r"(b0), "r"(b1));
}

#define CP16(dst, src) \
    asm volatile("cp.async.cg.shared.global [%0], [%1], 16;\n" :: "r"(dst), "l"(src))

template <int EPI, int BMt>
__global__ __launch_bounds__(128)
void hgemm_kernel(const __half* __restrict__ A, const __half2* __restrict__ B2,
                  const float* __restrict__ bias, float* __restrict__ C,
                  int M, int N, int K) {
    constexpr int BK = 32;
    constexpr int ASZW = BMt * 16;
    constexpr int BSZW = 16 * 128;
    constexpr int STG  = ASZW + BSZW;
    constexpr int MI   = BMt / 32;
    extern __shared__ unsigned smw[];

    int tid  = threadIdx.x;
    int lane = tid & 31;
    int warp = tid >> 5;
    int g    = lane >> 2;
    int tig  = lane & 3;
    int wm   = warp & 1;
    int wn   = warp >> 1;
    int rm   = wm * (BMt / 2);
    int cn   = wn * 64;

    const __half*  Ab  = A + (size_t)(blockIdx.y * BMt) * K;
    const __half2* Bb2 = B2 + (size_t)blockIdx.x * 128;

    float acc[MI][8][4];
    #pragma unroll
    for (int mi = 0; mi < MI; mi++)
        #pragma unroll
        for (int ni = 0; ni < 8; ni++)
            #pragma unroll
            for (int c = 0; c < 4; c++) acc[mi][ni][c] = 0.0f;

    unsigned sBase = (unsigned)__cvta_generic_to_shared(smw);

    auto issue = [&](int kt, int p) {
        unsigned sa = sBase + (unsigned)(p * STG) * 4u;
        unsigned sb = sa + (unsigned)ASZW * 4u;
        #pragma unroll
        for (int i = 0; i < BMt / 32; i++) {
            int lin = tid + i * 128;
            int m = lin >> 2, c = lin & 3;
            const __half* src = Ab + (size_t)m * K + kt + c * 8;
            unsigned dst = sa + (unsigned)(m * 16 + ((c ^ ((m >> 1) & 3)) << 2)) * 4u;
            CP16(dst, src);
        }
        #pragma unroll
        for (int i = 0; i < 4; i++) {
            int lin = tid + i * 128;
            int k2 = lin >> 5, c4 = lin & 31;
            const __half2* src = Bb2 + (size_t)(kt / 2 + k2) * N + c4 * 4;
            unsigned dst = sb + (unsigned)(k2 * 128 + ((c4 ^ (2 * (k2 & 3))) << 2)) * 4u;
            CP16(dst, src);
        }
        asm volatile("cp.async.commit_group;\n");
    };

    int ntiles = K / BK;
    issue(0, 0);
    issue(BK, 1);

    for (int t = 0; t < ntiles; t++) {
        int p = t % 3;
        asm volatile("cp.async.wait_group 1;\n");
        __syncthreads();
        if (t + 2 < ntiles) {
            issue((t + 2) * BK, (t + 2) % 3);
        } else {
            asm volatile("cp.async.commit_group;\n");
        }

        const unsigned* Ap = smw + p * STG;
        const unsigned* Bp = Ap + ASZW;
        #pragma unroll
        for (int ksi = 0; ksi < 2; ksi++) {
            unsigned af[MI][4], bf[8][2];
            #pragma unroll
            for (int mi = 0; mi < MI; mi++) {
                int m1 = rm + mi * 16 + g;
                int m2 = m1 + 8;
                unsigned s1 = (unsigned)((m1 >> 1) & 3);
                unsigned s2 = (unsigned)((m2 >> 1) & 3);
                unsigned c0 = (unsigned)(2 * ksi);
                af[mi][0] = Ap[m1 * 16 + (((c0    ) ^ s1) << 2) + tig];
                af[mi][1] = Ap[m2 * 16 + (((c0    ) ^ s2) << 2) + tig];
                af[mi][2] = Ap[m1 * 16 + (((c0 + 1) ^ s1) << 2) + tig];
                af[mi][3] = Ap[m2 * 16 + (((c0 + 1) ^ s2) << 2) + tig];
            }
            int k2b = ksi * 8;
            #pragma unroll
            for (int ni = 0; ni < 8; ni++) {
                unsigned nb = (unsigned)(cn + ni * 8 + g);
                bf[ni][0] = Bp[(k2b + tig)     * 128 + (nb ^ (unsigned)(8 * tig))];
                bf[ni][1] = Bp[(k2b + tig + 4) * 128 + (nb ^ (unsigned)(8 * tig))];
            }
            #pragma unroll
            for (int mi = 0; mi < MI; mi++)
                #pragma unroll
                for (int ni = 0; ni < 8; ni++)
                    mma_f16(acc[mi][ni],
                            af[mi][0], af[mi][1], af[mi][2], af[mi][3],
                            bf[ni][0], bf[ni][1]);
        }
        __syncthreads();
    }

    #pragma unroll
    for (int ni = 0; ni < 8; ni++) {
        int gc = blockIdx.x * 128 + cn + ni * 8 + 2 * tig;
        float bv0 = bias ? bias[gc]     : 0.0f;
        float bv1 = bias ? bias[gc + 1] : 0.0f;
        #pragma unroll
        for (int mi = 0; mi < MI; mi++) {
            int gr1 = blockIdx.y * BMt + rm + mi * 16 + g;
            int gr2 = gr1 + 8;
            float v00 = acc[mi][ni][0] + bv0;
            float v01 = acc[mi][ni][1] + bv1;
            float v10 = acc[mi][ni][2] + bv0;
            float v11 = acc[mi][ni][3] + bv1;
            if (EPI == 0) {
                *(float2*)(C + (size_t)gr1 * N + gc) = make_float2(v00, v01);
                *(float2*)(C + (size_t)gr2 * N + gc) = make_float2(v10, v11);
            } else if (EPI == 1) {
                float2* p1 = (float2*)(C + (size_t)gr1 * N + gc);
                float2* p2 = (float2*)(C + (size_t)gr2 * N + gc);
                float2 o1 = *p1, o2 = *p2;
                *p1 = make_float2(o1.x + v00, o1.y + v01);
                *p2 = make_float2(o2.x + v10, o2.y + v11);
            } else {
                const float is2 = 0.70710678118654752f;
                __half* Ch = (__half*)C;
                float g00 = 0.5f * v00 * (1.0f + erff(v00 * is2));
                float g01 = 0.5f * v01 * (1.0f + erff(v01 * is2));
                float g10 = 0.5f * v10 * (1.0f + erff(v10 * is2));
                float g11 = 0.5f * v11 * (1.0f + erff(v11 * is2));
                *(__half2*)(Ch + (size_t)gr1 * N + gc) = __floats2half2_rn(g00, g01);
                *(__half2*)(Ch + (size_t)gr2 * N + gc) = __floats2half2_rn(g10, g11);
            }
        }
    }
}

// ---------------------------------------------------------------------------
// FP16 tensor-core flash attention (m16n8k16). One CTA per (64q, head, batch).
// 4 warps; warp w owns query rows w*16..w*16+15.
// Smem (half2 words): Q/K/P rows stride 36 (bank 4g+tig unique);
// V k-pair-interleaved [32 k2][64 n] stride 72 (bank 8*tig+g unique).
// ---------------------------------------------------------------------------
#define QSTW 36
#define VSTW 72

__global__ __launch_bounds__(128)
void attn4_kernel(const float* __restrict__ qkv, __half* __restrict__ y) {
    extern __shared__ unsigned smA[];
    unsigned* Qs = smA;                    // [64][36]
    unsigned* Ks = Qs + 64 * QSTW;         // [64][36]
    unsigned* Ps = Ks + 64 * QSTW;         // [64][36]
    unsigned* Vs = Ps + 64 * QSTW;         // [32][72]

    int qb = blockIdx.x, h = blockIdx.y, b = blockIdx.z;
    int tid = threadIdx.x;
    int lane = tid & 31, w = tid >> 5;
    int g = lane >> 2, tig = lane & 3;

    const size_t rs = 3 * Dq;
    const float* qbase = qkv + ((size_t)(b * Tq + qb * 64)) * rs + h * HDq;

    // stage Q: 64x64 fp32 -> fp16 (scaled 1/8). 1024 float4 slots / 128 = 8 it.
    #pragma unroll
    for (int i = 0; i < 8; i++) {
        int f = tid + i * 128;
        int r = f >> 4, c4 = (f & 15) * 4;
        float4 v = *(const float4*)(qbase + (size_t)r * rs + c4);
        __half2 h0 = __floats2half2_rn(v.x * 0.125f, v.y * 0.125f);
        __half2 h1 = __floats2half2_rn(v.z * 0.125f, v.w * 0.125f);
        uint2 u; u.x = *(unsigned*)&h0; u.y = *(unsigned*)&h1;
        *(uint2*)&Qs[r * QSTW + (c4 >> 1)] = u;
    }

    float oacc[8][4];
    #pragma unroll
    for (int ni = 0; ni < 8; ni++)
        #pragma unroll
        for (int c = 0; c < 4; c++) oacc[ni][c] = 0.0f;
    float mrow0 = -CUDART_INF_F, mrow1 = -CUDART_INF_F;
    float lrow0 = 0.0f, lrow1 = 0.0f;

    int rloc0 = w * 16 + g;
    int rloc1 = rloc0 + 8;

    for (int kt = 0; kt <= qb; kt++) {
        __syncthreads();
        const float* kbase = qkv + ((size_t)(b * Tq + kt * 64)) * rs + Dq + h * HDq;
        const float* vbase = kbase + Dq;
        // stage K: [key row][k half2 words], rounded to fp16
        #pragma unroll
        for (int i = 0; i < 8; i++) {
            int f = tid + i * 128;
            int r = f >> 4, c4 = (f & 15) * 4;
            float4 kv = *(const float4*)(kbase + (size_t)r * rs + c4);
            __half2 h0 = __floats2half2_rn(kv.x, kv.y);
            __half2 h1 = __floats2half2_rn(kv.z, kv.w);
            uint2 u; u.x = *(unsigned*)&h0; u.y = *(unsigned*)&h1;
            *(uint2*)&Ks[r * QSTW + (c4 >> 1)] = u;
        }
        // stage V: pair-gather -> [k2][n] half2 = (V[2k2][n], V[2k2+1][n])
        #pragma unroll
        for (int i = 0; i < 4; i++) {
            int lin = tid + i * 128;
            int k2 = lin >> 4, c = (lin & 15) * 4;
            float4 va = *(const float4*)(vbase + (size_t)(2 * k2)     * rs + c);
            float4 vb = *(const float4*)(vbase + (size_t)(2 * k2 + 1) * rs + c);
            __half2 h0 = __floats2half2_rn(va.x, vb.x);
            __half2 h1 = __floats2half2_rn(va.y, vb.y);
            __half2 h2 = __floats2half2_rn(va.z, vb.z);
            __half2 h3 = __floats2half2_rn(va.w, vb.w);
            uint4 u;
            u.x = *(unsigned*)&h0; u.y = *(unsigned*)&h1;
            u.z = *(unsigned*)&h2; u.w = *(unsigned*)&h3;
            *(uint4*)&Vs[k2 * VSTW + c] = u;
        }
        __syncthreads();

        // ---- S = Q K^T : 4 k-steps of 16 ----
        float sacc[8][4];
        #pragma unroll
        for (int ni = 0; ni < 8; ni++)
            #pragma unroll
            for (int c = 0; c < 4; c++) sacc[ni][c] = 0.0f;
        #pragma unroll
        for (int ksi = 0; ksi < 4; ksi++) {
            int kw = ksi * 8;
            unsigned a0 = Qs[rloc0 * QSTW + kw + tig];
            unsigned a1 = Qs[rloc1 * QSTW + kw + tig];
            unsigned a2 = Qs[rloc0 * QSTW + kw + 4 + tig];
            unsigned a3 = Qs[rloc1 * QSTW + kw + 4 + tig];
            #pragma unroll
            for (int ni = 0; ni < 8; ni++) {
                int nr = ni * 8 + g;
                unsigned b0 = Ks[nr * QSTW + kw + tig];
                unsigned b1 = Ks[nr * QSTW + kw + 4 + tig];
                mma_f16(sacc[ni], a0, a1, a2, a3, b0, b1);
            }
        }

        // ---- causal mask on diagonal tile ----
        if (kt == qb) {
            #pragma unroll
            for (int ni = 0; ni < 8; ni++) {
                int c0 = ni * 8 + 2 * tig, c1 = c0 + 1;
                if (c0 > rloc0) sacc[ni][0] = -CUDART_INF_F;
                if (c1 > rloc0) sacc[ni][1] = -CUDART_INF_F;
                if (c0 > rloc1) sacc[ni][2] = -CUDART_INF_F;
                if (c1 > rloc1) sacc[ni][3] = -CUDART_INF_F;
            }
        }

        // ---- online softmax ----
        float mx0 = -CUDART_INF_F, mx1 = -CUDART_INF_F;
        #pragma unroll
        for (int ni = 0; ni < 8; ni++) {
            mx0 = fmaxf(mx0, fmaxf(sacc[ni][0], sacc[ni][1]));
            mx1 = fmaxf(mx1, fmaxf(sacc[ni][2], sacc[ni][3]));
        }
        mx0 = fmaxf(mx0, __shfl_xor_sync(0xffffffffu, mx0, 1));
        mx0 = fmaxf(mx0, __shfl_xor_sync(0xffffffffu, mx0, 2));
        mx1 = fmaxf(mx1, __shfl_xor_sync(0xffffffffu, mx1, 1));
        mx1 = fmaxf(mx1, __shfl_xor_sync(0xffffffffu, mx1, 2));

        float mn0 = fmaxf(mrow0, mx0);
        float mn1 = fmaxf(mrow1, mx1);
        float corr0 = __expf(mrow0 - mn0);
        float corr1 = __expf(mrow1 - mn1);

        float rs0 = 0.0f, rs1 = 0.0f;
        #pragma unroll
        for (int ni = 0; ni < 8; ni++) {
            __half2 h0 = __floats2half2_rn(__expf(sacc[ni][0] - mn0),
                                           __expf(sacc[ni][1] - mn0));
            __half2 h1 = __floats2half2_rn(__expf(sacc[ni][2] - mn1),
                                           __expf(sacc[ni][3] - mn1));
            rs0 += __low2float(h0) + __high2float(h0);
            rs1 += __low2float(h1) + __high2float(h1);
            Ps[rloc0 * QSTW + 4 * ni + tig] = *(unsigned*)&h0;
            Ps[rloc1 * QSTW + 4 * ni + tig] = *(unsigned*)&h1;
        }
        rs0 += __shfl_xor_sync(0xffffffffu, rs0, 1);
        rs0 += __shfl_xor_sync(0xffffffffu, rs0, 2);
        rs1 += __shfl_xor_sync(0xffffffffu, rs1, 1);
        rs1 += __shfl_xor_sync(0xffffffffu, rs1, 2);

        lrow0 = lrow0 * corr0 + rs0;
        lrow1 = lrow1 * corr1 + rs1;
        mrow0 = mn0; mrow1 = mn1;

        #pragma unroll
        for (int ni = 0; ni < 8; ni++) {
            oacc[ni][0] *= corr0; oacc[ni][1] *= corr0;
            oacc[ni][2] *= corr1; oacc[ni][3] *= corr1;
        }
        __syncwarp();

        // ---- O += P V : 4 k-steps of 16 (key dim) ----
        #pragma unroll
        for (int ksi = 0; ksi < 4; ksi++) {
            int kw = ksi * 8;
            unsigned a0 = Ps[rloc0 * QSTW + kw + tig];
            unsigned a1 = Ps[rloc1 * QSTW + kw + tig];
            unsigned a2 = Ps[rloc0 * QSTW + kw + 4 + tig];
            unsigned a3 = Ps[rloc1 * QSTW + kw + 4 + tig];
            #pragma unroll
            for (int ni = 0; ni < 8; ni++) {
                int n = ni * 8 + g;
                unsigned b0 = Vs[(kw + tig)     * VSTW + n];
                unsigned b1 = Vs[(kw + 4 + tig) * VSTW + n];
                mma_f16(oacc[ni], a0, a1, a2, a3, b0, b1);
            }
        }
        __syncwarp();
    }

    float inv0 = 1.0f / lrow0;
    float inv1 = 1.0f / lrow1;
    size_t row0 = (size_t)(b * Tq + qb * 64 + rloc0);
    size_t row1 = row0 + 8;
    #pragma unroll
    for (int ni = 0; ni < 8; ni++) {
        int col = h * HDq + ni * 8 + 2 * tig;
        *(__half2*)&y[row0 * Dq + col] =
            __floats2half2_rn(oacc[ni][0] * inv0, oacc[ni][1] * inv0);
        *(__half2*)&y[row1 * Dq + col] =
            __floats2half2_rn(oacc[ni][2] * inv1, oacc[ni][3] * inv1);
    }
}

// ---------------------------------------------------------------------------
// Launch
// ---------------------------------------------------------------------------
extern "C" void kernel_launch(void* const* d_in, const int* in_sizes, int n_in,
                              void* d_out, int out_size) {
    const int*   idx     = (const int*)  d_in[0];
    const float* tok_emb = (const float*)d_in[1];
    const float* ln1_s   = (const float*)d_in[2];
    const float* ln1_b   = (const float*)d_in[3];
    const float* qkv_w   = (const float*)d_in[4];
    const float* qkv_b   = (const float*)d_in[5];
    const float* out_w   = (const float*)d_in[6];
    const float* out_b   = (const float*)d_in[7];
    const float* ln2_s   = (const float*)d_in[8];
    const float* ln2_b   = (const float*)d_in[9];
    const float* mlp_w1  = (const float*)d_in[10];
    const float* mlp_b1  = (const float*)d_in[11];
    const float* mlp_w2  = (const float*)d_in[12];
    const float* mlp_b2  = (const float*)d_in[13];
    const float* lnf_s   = (const float*)d_in[14];
    const float* lnf_b   = (const float*)d_in[15];
    const float* head_w  = (const float*)d_in[16];
    float* logits = (float*)d_out;

    float *x, *qkv;
    __half *lnh, *yh, *ffh;
    __half2 *wqkv, *wout, *wm1, *wm2, *whd;
    cudaGetSymbolAddress((void**)&x,    g_x);
    cudaGetSymbolAddress((void**)&qkv,  g_qkv);
    cudaGetSymbolAddress((void**)&lnh,  g_lnh);
    cudaGetSymbolAddress((void**)&yh,   g_yh);
    cudaGetSymbolAddress((void**)&ffh,  g_ffh);
    cudaGetSymbolAddress((void**)&wqkv, g_wqkv_h);
    cudaGetSymbolAddress((void**)&wout, g_wout_h);
    cudaGetSymbolAddress((void**)&wm1,  g_wm1_h);
    cudaGetSymbolAddress((void**)&wm2,  g_wm2_h);
    cudaGetSymbolAddress((void**)&whd,  g_whd_h);

    const int smem128 = 3 * (128 * 16 + 16 * 128) * (int)sizeof(unsigned);  // 48 KB
    const int smem64  = 3 * ( 64 * 16 + 16 * 128) * (int)sizeof(unsigned);  // 36 KB
    cudaFuncSetAttribute((const void*)hgemm_kernel<0, 128>,
                         cudaFuncAttributeMaxDynamicSharedMemorySize, smem128);
    cudaFuncSetAttribute((const void*)hgemm_kernel<2, 128>,
                         cudaFuncAttributeMaxDynamicSharedMemorySize, smem128);
    cudaFuncSetAttribute((const void*)hgemm_kernel<1, 64>,
                         cudaFuncAttributeMaxDynamicSharedMemorySize, smem64);
    const int attn_smem = (3 * 64 * QSTW + 32 * VSTW) * (int)sizeof(unsigned); // 36 KB
    cudaFuncSetAttribute(attn4_kernel,
                         cudaFuncAttributeMaxDynamicSharedMemorySize, attn_smem);

    // weight convert: fp32 [K][N] -> half2 [K/2][N]; 3D grid (n4, k2, layer)
    auto cvt = [](const float* src, __half2* dst, int K, int N, int L) {
        int n4 = N / 4;
        dim3 grid((n4 + 255) / 256, K / 2, L);
        w2h4_kernel<<<grid, 256>>>((const float4*)src, (uint4*)dst, K, N);
    };
    cvt(qkv_w,  wqkv, Dq,  3 * Dq, Lq);
    cvt(out_w,  wout, Dq,  Dq,     Lq);
    cvt(mlp_w1, wm1,  Dq,  FFq,    Lq);
    cvt(mlp_w2, wm2,  FFq, Dq,     Lq);
    cvt(head_w, whd,  Dq,  Vq,     1);

    embed_kernel<<<Rq, 256>>>(idx, tok_emb, x);

    for (int l = 0; l < Lq; l++) {
        ln_kernel<<<Rq / 8, 256>>>(x, ln1_s + (size_t)l * Dq, ln1_b + (size_t)l * Dq, lnh);
        // qkv: N=3072
        hgemm_kernel<0, 128><<<dim3(3 * Dq / 128, Rq / 128), 128, smem128>>>(
            lnh, wqkv + (size_t)l * (Dq / 2) * 3 * Dq, qkv_b + (size_t)l * 3 * Dq,
            qkv, Rq, 3 * Dq, Dq);
        attn4_kernel<<<dim3(Tq / 64, Hq, Bq), 128, attn_smem>>>(qkv, yh);
        // out-proj: N=1024, BMt=64
        hgemm_kernel<1, 64><<<dim3(Dq / 128, Rq / 64), 128, smem64>>>(
            yh, wout + (size_t)l * (Dq / 2) * Dq, out_b + (size_t)l * Dq,
            x, Rq, Dq, Dq);
        ln_kernel<<<Rq / 8, 256>>>(x, ln2_s + (size_t)l * Dq, ln2_b + (size_t)l * Dq, lnh);
        // mlp1: N=4096, gelu -> fp16 ff
        hgemm_kernel<2, 128><<<dim3(FFq / 128, Rq / 128), 128, smem128>>>(
            lnh, wm1 + (size_t)l * (Dq / 2) * FFq, mlp_b1 + (size_t)l * FFq,
            (float*)ffh, Rq, FFq, Dq);
        // mlp2: N=1024, K=4096, BMt=64
        hgemm_kernel<1, 64><<<dim3(Dq / 128, Rq / 64), 128, smem64>>>(
            ffh, wm2 + (size_t)l * (FFq / 2) * Dq, mlp_b2 + (size_t)l * Dq,
            x, Rq, Dq, FFq);
    }

    ln_kernel<<<Rq / 8, 256>>>(x, lnf_s, lnf_b, lnh);
    // head: N=32000
    hgemm_kernel<0, 128><<<dim3(Vq / 128, Rq / 128), 128, smem128>>>(
        lnh, whd, (const float*)nullptr, logits, Rq, Vq, Dq);
}